// round 14
// baseline (speedup 1.0000x reference)
#include <cuda_runtime.h>
#include <cuda_bf16.h>
#include <math.h>

#define T_ 32
#define B_ 64
#define S_ 64
#define D_ 1024
#define D4_ 4096
#define TB_ 2048
#define BD_ (B_ * D_)

// ---------------- scratch (device globals) ----------------
__device__ float g_xg[TB_ * D4_];
__device__ float g_q [TB_ * D_];

__device__ __align__(16) __nv_bfloat16 g_x0h[TB_ * D_], g_x0l[TB_ * D_];
__device__ __align__(16) __nv_bfloat16 g_sh [TB_ * D_], g_sl [TB_ * D_];
__device__ __align__(16) __nv_bfloat16 g_h0h[2 * BD_],  g_h0l[2 * BD_];
__device__ __align__(16) __nv_bfloat16 g_cath[TB_ * 2 * D_], g_catl[TB_ * 2 * D_];

__device__ __align__(16) __nv_bfloat16 g_whhh0[D4_ * D_], g_whhl0[D4_ * D_];
__device__ __align__(16) __nv_bfloat16 g_whhh1[D4_ * D_], g_whhl1[D4_ * D_];
__device__ __align__(16) __nv_bfloat16 g_wihh0[D4_ * D_], g_wihl0[D4_ * D_];
__device__ __align__(16) __nv_bfloat16 g_wihh1[D4_ * D_], g_wihl1[D4_ * D_];
__device__ __align__(16) __nv_bfloat16 g_winh[D_ * D_],   g_winl[D_ * D_];
__device__ __align__(16) __nv_bfloat16 g_wouth[D_ * 2 * D_], g_woutl[D_ * 2 * D_];

__device__ unsigned g_done;
__device__ unsigned g_flag[128];   // per-block completed-step counter

// ---------------- asm helpers ----------------
__device__ __forceinline__ void mma16816(float* d, const unsigned* a, const unsigned* b)
{
    asm volatile(
        "mma.sync.aligned.m16n8k16.row.col.f32.bf16.bf16.f32 "
        "{%0,%1,%2,%3}, {%4,%5,%6,%7}, {%8,%9}, {%0,%1,%2,%3};"
        : "+f"(d[0]), "+f"(d[1]), "+f"(d[2]), "+f"(d[3])
        : "r"(a[0]), "r"(a[1]), "r"(a[2]), "r"(a[3]),
          "r"(b[0]), "r"(b[1]));
}
__device__ __forceinline__ void ldsm_x4(unsigned* r, unsigned addr)
{
    asm volatile("ldmatrix.sync.aligned.m8n8.x4.shared.b16 {%0,%1,%2,%3}, [%4];"
                 : "=r"(r[0]), "=r"(r[1]), "=r"(r[2]), "=r"(r[3]) : "r"(addr));
}
__device__ __forceinline__ void ldsm_x2(unsigned* r, unsigned addr)
{
    asm volatile("ldmatrix.sync.aligned.m8n8.x2.shared.b16 {%0,%1}, [%2];"
                 : "=r"(r[0]), "=r"(r[1]) : "r"(addr));
}
__device__ __forceinline__ void cpa16(unsigned saddr, const void* g)
{
    asm volatile("cp.async.cg.shared.global [%0], [%1], 16;" :: "r"(saddr), "l"(g) : "memory");
}
__device__ __forceinline__ void cp_commit() { asm volatile("cp.async.commit_group;" ::: "memory"); }
__device__ __forceinline__ void cp_wait0()  { asm volatile("cp.async.wait_group 0;" ::: "memory"); }
__device__ __forceinline__ unsigned ld_acq(const unsigned* p)
{
    unsigned v;
    asm volatile("ld.acquire.gpu.global.u32 %0, [%1];" : "=r"(v) : "l"(p) : "memory");
    return v;
}

__device__ __forceinline__ void split_store4(float4 v,
                                             __nv_bfloat162* hp,
                                             __nv_bfloat162* lp)
{
    float hx = __bfloat162float(__float2bfloat16(v.x));
    float hy = __bfloat162float(__float2bfloat16(v.y));
    float hz = __bfloat162float(__float2bfloat16(v.z));
    float hw = __bfloat162float(__float2bfloat16(v.w));
    hp[0] = __nv_bfloat162(__float2bfloat16(hx), __float2bfloat16(hy));
    hp[1] = __nv_bfloat162(__float2bfloat16(hz), __float2bfloat16(hw));
    lp[0] = __nv_bfloat162(__float2bfloat16(v.x - hx), __float2bfloat16(v.y - hy));
    lp[1] = __nv_bfloat162(__float2bfloat16(v.z - hz), __float2bfloat16(v.w - hw));
}

// ---------------- fused split: all 6 weights + both h0 slices, one launch ---
#define RW  1048576
#define RWIN 262144
#define RWOUT 524288
#define RH 16384
#define FS_TOTAL (4 * RW + RWIN + RWOUT + 2 * RH)

__global__ __launch_bounds__(256)
void fused_split(const float* __restrict__ whh0, const float* __restrict__ wih0,
                 const float* __restrict__ whh1, const float* __restrict__ wih1,
                 const float* __restrict__ w_in, const float* __restrict__ w_out,
                 const float* __restrict__ h0,
                 __nv_bfloat16* whhh0, __nv_bfloat16* whhl0,
                 __nv_bfloat16* wihh0, __nv_bfloat16* wihl0,
                 __nv_bfloat16* whhh1, __nv_bfloat16* whhl1,
                 __nv_bfloat16* wihh1, __nv_bfloat16* wihl1,
                 __nv_bfloat16* winh,  __nv_bfloat16* winl,
                 __nv_bfloat16* wouth, __nv_bfloat16* woutl,
                 __nv_bfloat16* h0h,   __nv_bfloat16* h0l)
{
    long idx = (long)blockIdx.x * 256 + threadIdx.x;
    if (idx >= FS_TOTAL) return;
    const float* src;
    __nv_bfloat16 *hi, *lo;
    long l = idx;
    if (l < RW)                    { src = whh0; hi = whhh0; lo = whhl0; }
    else if ((l -= RW) < RW)       { src = wih0; hi = wihh0; lo = wihl0; }
    else if ((l -= RW) < RW)       { src = whh1; hi = whhh1; lo = whhl1; }
    else if ((l -= RW) < RW)       { src = wih1; hi = wihh1; lo = wihl1; }
    else if ((l -= RW) < RWIN)     { src = w_in; hi = winh;  lo = winl;  }
    else if ((l -= RWIN) < RWOUT)  { src = w_out; hi = wouth; lo = woutl; }
    else if ((l -= RWOUT) < 2 * RH){ src = h0;   hi = h0h;   lo = h0l;   }
    else return;
    float4 v = ((const float4*)src)[l];
    split_store4(v, (__nv_bfloat162*)hi + l * 2, (__nv_bfloat162*)lo + l * 2);
}

__global__ void embed_kernel(const int* __restrict__ tok,
                             const float* __restrict__ emb,
                             __nv_bfloat16* __restrict__ xh,
                             __nv_bfloat16* __restrict__ xl)
{
    int tb = blockIdx.x;
    int t4 = threadIdx.x;
    int tk = tok[tb];
    float4 v = make_float4(0.f, 0.f, 0.f, 0.f);
    if (tk != 0) v = ((const float4*)(emb + (size_t)tk * D_))[t4];
    split_store4(v, (__nv_bfloat162*)(xh + (size_t)tb * D_) + t4 * 2,
                    (__nv_bfloat162*)(xl + (size_t)tb * D_) + t4 * 2);
}

// ---------------- bf16 tensor GEMM: single-sweep 3-term compensation --------
#define HG_SMEM 65536
template<int EPI>
__global__ __launch_bounds__(256, 2)
void hgemm_nt(const __nv_bfloat16* __restrict__ Ahi,
              const __nv_bfloat16* __restrict__ Alo,
              const __nv_bfloat16* __restrict__ Bhi,
              const __nv_bfloat16* __restrict__ Blo,
              float* __restrict__ C, int M, int N, int K,
              const float* __restrict__ bias1, const float* __restrict__ bias2)
{
    extern __shared__ char hsm[];
    const unsigned SA = (unsigned)__cvta_generic_to_shared(hsm);
    const unsigned SB = SA + 32768;

    const int tid  = threadIdx.x;
    const int wid  = tid >> 5;
    const int lane = tid & 31;
    const int gid  = lane >> 2;
    const int tig  = lane & 3;
    const int wm   = wid >> 2;
    const int wn   = wid & 3;
    const int bm   = blockIdx.y * 128;
    const int bn   = blockIdx.x * 128;
    const int KC   = K >> 5;

    float acc[4][4][4];
#pragma unroll
    for (int mt = 0; mt < 4; mt++)
#pragma unroll
        for (int nt = 0; nt < 4; nt++)
#pragma unroll
            for (int r = 0; r < 4; r++) acc[mt][nt][r] = 0.f;

    auto issue = [&](int it) {
        int kc = it << 5;
        int buf = it & 1;
#pragma unroll
        for (int j = 0; j < 8; j++) {
            int id   = tid + (j << 8);
            int mat  = id >> 9;
            int e    = id & 511;
            int half = e & 1;
            int row  = (e >> 1) & 127;
            int kh   = e >> 8;
            const __nv_bfloat16* src =
                (mat == 0) ? Ahi : (mat == 1) ? Alo : (mat == 2) ? Bhi : Blo;
            int grow = ((mat < 2) ? bm : bn) + row;
            src += (size_t)grow * K + kc + (kh << 4) + (half << 3);
            unsigned dst = ((mat < 2) ? SA : SB) + (unsigned)(buf * 16384 +
                           (mat & 1) * 8192 + (kh << 12) + (row << 5) + (half << 4));
            cpa16(dst, src);
        }
        cp_commit();
    };

    const unsigned aoff = (unsigned)(((wm << 6) + (lane & 15)) * 32 + (((lane >> 4) & 1) << 4));
    const unsigned boff = (unsigned)(((wn << 5) + (lane & 7)) * 32 + (((lane >> 3) & 1) << 4));

    issue(0);
    for (int it = 0; it < KC; it++) {
        cp_wait0();
        __syncthreads();
        if (it + 1 < KC) issue(it + 1);
        const unsigned ba = SA + (unsigned)((it & 1) * 16384);
        const unsigned bb = SB + (unsigned)((it & 1) * 16384);
#pragma unroll
        for (int kh = 0; kh < 2; kh++) {
            unsigned ahi[4][4], alo[4][4];
#pragma unroll
            for (int mt = 0; mt < 4; mt++) {
                ldsm_x4(ahi[mt], ba + (kh << 12) + (unsigned)(mt << 9) + aoff);
                ldsm_x4(alo[mt], ba + 8192 + (kh << 12) + (unsigned)(mt << 9) + aoff);
            }
#pragma unroll
            for (int nt = 0; nt < 4; nt++) {
                unsigned bh[2], bl[2];
                ldsm_x2(bh, bb + (kh << 12) + (unsigned)(nt << 8) + boff);
                ldsm_x2(bl, bb + 8192 + (kh << 12) + (unsigned)(nt << 8) + boff);
#pragma unroll
                for (int mt = 0; mt < 4; mt++) {
                    mma16816(acc[mt][nt], ahi[mt], bh);
                    mma16816(acc[mt][nt], alo[mt], bh);
                    mma16816(acc[mt][nt], ahi[mt], bl);
                }
            }
        }
    }

#pragma unroll
    for (int mt = 0; mt < 4; mt++)
#pragma unroll
        for (int nt = 0; nt < 4; nt++)
#pragma unroll
            for (int rp = 0; rp < 2; rp++) {
                int row = bm + (wm << 6) + (mt << 4) + gid + (rp << 3);
                int col = bn + (wn << 5) + (nt << 3) + (tig << 1);
                float v0 = acc[mt][nt][rp * 2];
                float v1 = acc[mt][nt][rp * 2 + 1];
                if (EPI == 1) {
                    v0 += __ldg(bias1 + col) + __ldg(bias2 + col);
                    v1 += __ldg(bias1 + col + 1) + __ldg(bias2 + col + 1);
                }
                if (EPI == 2) { v0 = tanhf(v0); v1 = tanhf(v1); }
                float2 o; o.x = v0; o.y = v1;
                *(float2*)(C + (size_t)row * N + col) = o;
            }
}

// ---------------- persistent LSTM layer: producer-flag sync -----------------
// R13 structure (512 thr, 2-way k-split) but grid_bar replaced by per-block
// flags: staging chunk ck of step t waits only on the 16 producer blocks of
// those h columns (8 per k-half). Producers publish after their slice store.
#define LSTM_SMEM 215296

__global__ __launch_bounds__(512, 1)
void lstm_layer_persist(const __nv_bfloat16* __restrict__ h0h,
                        const __nv_bfloat16* __restrict__ h0l,
                        const __nv_bfloat16* __restrict__ whi,
                        const __nv_bfloat16* __restrict__ wlo,
                        const float* __restrict__ c0,
                        const float* __restrict__ xg,
                        __nv_bfloat16* __restrict__ shh,
                        __nv_bfloat16* __restrict__ shl,
                        float* __restrict__ hn_out,
                        float* __restrict__ cn_out)
{
    extern __shared__ char smem[];
    float* red2 = (float*)(smem + 196608);
    float* cs   = (float*)(smem + 212992);

    const int tid  = threadIdx.x;
    const int wid  = tid >> 5;
    const int lane = tid & 31;
    const int kh2  = wid >> 3;
    const int w8   = wid & 7;
    const int mt   = w8 & 3;
    const int nh   = w8 >> 2;
    const int d0   = blockIdx.x << 3;
    const int pb   = tid >> 3;
    const int pd   = tid & 7;

    const unsigned WS = (unsigned)__cvta_generic_to_shared(smem);
    const unsigned HS = WS + 131072;

#pragma unroll
    for (int i = 0; i < 16; i++) {
        int id   = tid + (i << 9);
        int half = id & 1;
        int r    = (id >> 1) & 31;
        int k16  = (id >> 6) & 63;
        int hl   = id >> 12;
        int grow = ((r >> 3) << 10) + d0 + (r & 7);
        const __nv_bfloat16* src =
            (hl ? wlo : whi) + (size_t)grow * D_ + (k16 << 4) + (half << 3);
        cpa16(WS + hl * 65536 + (k16 << 10) + (r << 5) + (half << 4), src);
    }
    cp_commit();
    cs[tid] = __ldg(c0 + (size_t)pb * D_ + d0 + pd);
    cp_wait0();
    __syncthreads();

    const unsigned aoff  = (unsigned)(((mt << 4) + (lane & 15)) * 32 + (((lane >> 4) & 1) << 4));
    const unsigned boff0 = (unsigned)(((nh << 4) + (lane & 7)) * 32 + (((lane >> 3) & 1) << 4));
    const unsigned boff1 = boff0 + 8 * 32;

    // pointwise inverse-mapping indices
    int pidx[4];
#pragma unroll
    for (int g = 0; g < 4; g++) {
        int n = (g << 3) + pd;
        int pmt = pb >> 4, pgid = pb & 7, prb = (pb >> 3) & 1;
        int pnh = n >> 4, pnt = (n >> 3) & 1, ptig = (n >> 1) & 3, prn = n & 1;
        int pw8 = (pnh << 2) | pmt;
        int pln = (pgid << 2) | ptig;
        int pr  = (prb << 1) | prn;
        pidx[g] = (pw8 << 8) + (pln << 3) + (pnt << 2) + pr;
    }

    for (int t = 0; t < T_; t++) {
        const __nv_bfloat16* ah = t ? shh + (size_t)(t - 1) * BD_ : h0h;
        const __nv_bfloat16* al = t ? shl + (size_t)(t - 1) * BD_ : h0l;
        const float* xgt = xg + (size_t)t * B_ * D4_;

        float xv[4];
#pragma unroll
        for (int g = 0; g < 4; g++)
            xv[g] = __ldg(xgt + (size_t)pb * D4_ + (g << 10) + d0 + pd);

        float acc[2][4];
#pragma unroll
        for (int nt = 0; nt < 2; nt++)
#pragma unroll
            for (int r = 0; r < 4; r++) acc[nt][r] = 0.f;

        // wait for the 16 producer blocks of staging group ii (skip at t=0)
        auto waitgrp = [&](int ii) {
            if (t == 0) return;
            if (tid < 16) {
                int p = (tid < 8) ? ((ii << 3) + tid) : (64 + (ii << 3) + (tid - 8));
                const unsigned* fp = &g_flag[p];
                while (ld_acq(fp) < (unsigned)t) { }
            }
        };

        auto issue = [&](int ii) {
            unsigned bA = (unsigned)((ii & 1) * 16384);
#pragma unroll
            for (int j = 0; j < 4; j++) {
                int id   = tid + (j << 9);
                int ch   = id >> 10;
                int e    = id & 1023;
                int half = e & 1;
                int row  = (e >> 1) & 63;
                int k16l = (e >> 7) & 3;
                int hl   = e >> 9;
                int ck   = (ch << 3) + ii;
                const __nv_bfloat16* src =
                    (hl ? al : ah) + (size_t)row * D_ + (ck << 6) + (k16l << 4) + (half << 3);
                cpa16(HS + (unsigned)(ch * 32768) + bA + (unsigned)(hl * 8192 + (k16l << 11) + (row << 5) + (half << 4)), src);
            }
            cp_commit();
        };

        waitgrp(0);
        __syncthreads();
        issue(0);
        for (int i = 0; i < 8; i++) {
            cp_wait0();
            if (i < 7) waitgrp(i + 1);
            __syncthreads();
            if (i < 7) issue(i + 1);
            const unsigned hb = HS + (unsigned)(kh2 * 32768 + (i & 1) * 16384);
#pragma unroll
            for (int k16l = 0; k16l < 4; k16l++) {
                unsigned ahi[4], alo[4], bh0[2], bh1[2], bl0[2], bl1[2];
                ldsm_x4(ahi, hb + (k16l << 11) + aoff);
                ldsm_x4(alo, hb + 8192 + (k16l << 11) + aoff);
                unsigned kb = WS + (unsigned)(((kh2 << 5) + (i << 2) + k16l) << 10);
                ldsm_x2(bh0, kb + boff0);
                ldsm_x2(bh1, kb + boff1);
                ldsm_x2(bl0, kb + 65536 + boff0);
                ldsm_x2(bl1, kb + 65536 + boff1);
                mma16816(acc[0], ahi, bh0);
                mma16816(acc[1], ahi, bh1);
                mma16816(acc[0], alo, bh0);
                mma16816(acc[1], alo, bh1);
                mma16816(acc[0], ahi, bl0);
                mma16816(acc[1], ahi, bl1);
            }
        }

        // store partials to this half's region
        {
            float4* r2 = (float4*)(red2 + (kh2 << 11));
            int base4 = ((w8 << 8) + (lane << 3)) >> 2;
            r2[base4]     = make_float4(acc[0][0], acc[0][1], acc[0][2], acc[0][3]);
            r2[base4 + 1] = make_float4(acc[1][0], acc[1][1], acc[1][2], acc[1][3]);
        }
        __syncthreads();

        // pointwise
        {
            float ig = red2[pidx[0]] + red2[2048 + pidx[0]] + xv[0];
            float fg = red2[pidx[1]] + red2[2048 + pidx[1]] + xv[1];
            float gg = red2[pidx[2]] + red2[2048 + pidx[2]] + xv[2];
            float og = red2[pidx[3]] + red2[2048 + pidx[3]] + xv[3];
            float ci = cs[tid];
            float i_ = 1.f / (1.f + __expf(-ig));
            float f_ = 1.f / (1.f + __expf(-fg));
            float o_ = 1.f / (1.f + __expf(-og));
            float cn = f_ * ci + i_ * tanhf(gg);
            float hn = o_ * tanhf(cn);
            cs[tid] = cn;
            size_t idx = (size_t)t * BD_ + (size_t)pb * D_ + d0 + pd;
            float hh = __bfloat162float(__float2bfloat16(hn));
            shh[idx] = __float2bfloat16(hh);
            shl[idx] = __float2bfloat16(hn - hh);
            if (t == T_ - 1) hn_out[(size_t)pb * D_ + d0 + pd] = hn;
        }

        // publish this block's step-t slice
        __syncthreads();
        if (tid == 0) {
            __threadfence();
            atomicExch(&g_flag[blockIdx.x], (unsigned)(t + 1));
        }
    }

    cn_out[(size_t)pb * D_ + d0 + pd] = cs[tid];

    // end handshake: last block resets flags for the next launch / replay
    __threadfence();
    __syncthreads();
    if (tid == 0) {
        unsigned d = atomicAdd(&g_done, 1u) + 1;
        if (d == gridDim.x) {
            for (int i = 0; i < 128; i++) g_flag[i] = 0;
            g_done = 0;
            __threadfence();
        }
    }
}

// ---------------- attention ----------------
__global__ __launch_bounds__(256)
void attn_kernel(const float* __restrict__ q,
                 const float* __restrict__ ctx,
                 const __nv_bfloat16* __restrict__ xh,
                 const __nv_bfloat16* __restrict__ xl,
                 __nv_bfloat16* __restrict__ cath,
                 __nv_bfloat16* __restrict__ catl,
                 float* __restrict__ attn_out)
{
    const int b = blockIdx.x;
    const int t = blockIdx.y;
    const int tb = t * B_ + b;
    __shared__ float qs[D_];
    __shared__ float sc[S_];

    const int tid = threadIdx.x;
    const int warp = tid >> 5, lane = tid & 31;

    ((float4*)qs)[tid] = ((const float4*)(q + (size_t)tb * D_))[tid];
    __syncthreads();

#pragma unroll
    for (int si = 0; si < 8; si++) {
        int s = warp * 8 + si;
        const float4* crow = (const float4*)(ctx + (size_t)(s * B_ + b) * D_);
        float sum = 0.f;
#pragma unroll
        for (int i = 0; i < 8; i++) {
            float4 cv = crow[lane + 32 * i];
            float4 qv = ((const float4*)qs)[lane + 32 * i];
            sum = fmaf(cv.x, qv.x, sum);
            sum = fmaf(cv.y, qv.y, sum);
            sum = fmaf(cv.z, qv.z, sum);
            sum = fmaf(cv.w, qv.w, sum);
        }
#pragma unroll
        for (int off = 16; off; off >>= 1)
            sum += __shfl_down_sync(0xffffffffu, sum, off);
        if (lane == 0) sc[s] = sum;
    }
    __syncthreads();

    if (warp == 0) {
        float v0 = sc[lane], v1 = sc[lane + 32];
        float m = fmaxf(v0, v1);
#pragma unroll
        for (int off = 16; off; off >>= 1)
            m = fmaxf(m, __shfl_xor_sync(0xffffffffu, m, off));
        float e0 = __expf(v0 - m), e1 = __expf(v1 - m);
        float ssum = e0 + e1;
#pragma unroll
        for (int off = 16; off; off >>= 1)
            ssum += __shfl_xor_sync(0xffffffffu, ssum, off);
        float inv = 1.f / ssum;
        sc[lane] = e0 * inv;
        sc[lane + 32] = e1 * inv;
    }
    __syncthreads();

    float4 accv = make_float4(0.f, 0.f, 0.f, 0.f);
    for (int s = 0; s < S_; s++) {
        float a = sc[s];
        float4 cv = ((const float4*)(ctx + (size_t)(s * B_ + b) * D_))[tid];
        accv.x = fmaf(a, cv.x, accv.x);
        accv.y = fmaf(a, cv.y, accv.y);
        accv.z = fmaf(a, cv.z, accv.z);
        accv.w = fmaf(a, cv.w, accv.w);
    }
    __nv_bfloat162* ch = (__nv_bfloat162*)(cath + (size_t)tb * 2 * D_);
    __nv_bfloat162* cl = (__nv_bfloat162*)(catl + (size_t)tb * 2 * D_);
    split_store4(accv, ch + tid * 2, cl + tid * 2);

    const unsigned* xhu = (const unsigned*)(xh + (size_t)tb * D_);
    const unsigned* xlu = (const unsigned*)(xl + (size_t)tb * D_);
    unsigned* chu = (unsigned*)(cath + (size_t)tb * 2 * D_ + D_);
    unsigned* clu = (unsigned*)(catl + (size_t)tb * 2 * D_ + D_);
    chu[tid] = xhu[tid]; chu[tid + 256] = xhu[tid + 256];
    clu[tid] = xlu[tid]; clu[tid + 256] = xlu[tid + 256];

    if (t == T_ - 1 && tid < S_) attn_out[b * S_ + tid] = sc[tid];
}

// ---------------- launch ----------------
extern "C" void kernel_launch(void* const* d_in, const int* in_sizes, int n_in,
                              void* d_out, int out_size)
{
    (void)in_sizes; (void)n_in; (void)out_size;

    const int*   input = (const int*)  d_in[0];
    const float* h0    = (const float*)d_in[1];
    const float* c0    = (const float*)d_in[2];
    const float* ctx   = (const float*)d_in[3];
    const float* emb   = (const float*)d_in[5];
    const float* wih0  = (const float*)d_in[6];
    const float* whh0  = (const float*)d_in[7];
    const float* bih0  = (const float*)d_in[8];
    const float* bhh0  = (const float*)d_in[9];
    const float* wih1  = (const float*)d_in[10];
    const float* whh1  = (const float*)d_in[11];
    const float* bih1  = (const float*)d_in[12];
    const float* bhh1  = (const float*)d_in[13];
    const float* w_in  = (const float*)d_in[14];
    const float* w_out = (const float*)d_in[15];

    float* out      = (float*)d_out;
    float* out_hn   = out + (size_t)TB_ * D_;
    float* out_cn   = out_hn + (size_t)2 * BD_;
    float* out_attn = out_cn + (size_t)2 * BD_;

    float *xg, *q;
    cudaGetSymbolAddress((void**)&xg, g_xg);
    cudaGetSymbolAddress((void**)&q,  g_q);

    __nv_bfloat16 *x0h, *x0l, *sh, *sl, *h0h, *h0l, *cath, *catl;
    __nv_bfloat16 *whhh0, *whhl0, *whhh1, *whhl1;
    __nv_bfloat16 *wihh0, *wihl0, *wihh1, *wihl1, *winh, *winl, *wouth, *woutl;
    cudaGetSymbolAddress((void**)&x0h, g_x0h);   cudaGetSymbolAddress((void**)&x0l, g_x0l);
    cudaGetSymbolAddress((void**)&sh,  g_sh);    cudaGetSymbolAddress((void**)&sl,  g_sl);
    cudaGetSymbolAddress((void**)&h0h, g_h0h);   cudaGetSymbolAddress((void**)&h0l, g_h0l);
    cudaGetSymbolAddress((void**)&cath, g_cath); cudaGetSymbolAddress((void**)&catl, g_catl);
    cudaGetSymbolAddress((void**)&whhh0, g_whhh0); cudaGetSymbolAddress((void**)&whhl0, g_whhl0);
    cudaGetSymbolAddress((void**)&whhh1, g_whhh1); cudaGetSymbolAddress((void**)&whhl1, g_whhl1);
    cudaGetSymbolAddress((void**)&wihh0, g_wihh0); cudaGetSymbolAddress((void**)&wihl0, g_wihl0);
    cudaGetSymbolAddress((void**)&wihh1, g_wihh1); cudaGetSymbolAddress((void**)&wihl1, g_wihl1);
    cudaGetSymbolAddress((void**)&winh,  g_winh);  cudaGetSymbolAddress((void**)&winl,  g_winl);
    cudaGetSymbolAddress((void**)&wouth, g_wouth); cudaGetSymbolAddress((void**)&woutl, g_woutl);

    static int smem_set = 0;
    if (!smem_set) {
        cudaFuncSetAttribute(lstm_layer_persist,
                             cudaFuncAttributeMaxDynamicSharedMemorySize, LSTM_SMEM);
        cudaFuncSetAttribute(hgemm_nt<0>,
                             cudaFuncAttributeMaxDynamicSharedMemorySize, HG_SMEM);
        cudaFuncSetAttribute(hgemm_nt<1>,
                             cudaFuncAttributeMaxDynamicSharedMemorySize, HG_SMEM);
        cudaFuncSetAttribute(hgemm_nt<2>,
                             cudaFuncAttributeMaxDynamicSharedMemorySize, HG_SMEM);
        smem_set = 1;
    }

    const size_t BD = (size_t)BD_;

    // ---- all splits in ONE launch ----
    fused_split<<<(FS_TOTAL + 255) / 256, 256>>>(
        whh0, wih0, whh1, wih1, w_in, w_out, h0,
        whhh0, whhl0, wihh0, wihl0, whhh1, whhl1, wihh1, wihl1,
        winh, winl, wouth, woutl, h0h, h0l);
    embed_kernel<<<TB_, 256>>>(input, emb, x0h, x0l);

    // ---- layer 0 ----
    hgemm_nt<1><<<dim3(D4_ / 128, TB_ / 128), 256, HG_SMEM>>>(
        x0h, x0l, wihh0, wihl0, xg, TB_, D4_, D_, bih0, bhh0);
    lstm_layer_persist<<<128, 512, LSTM_SMEM>>>(
        h0h, h0l, whhh0, whhl0, c0, xg, sh, sl, out_hn, out_cn);

    // ---- layer 1 ----
    hgemm_nt<1><<<dim3(D4_ / 128, TB_ / 128), 256, HG_SMEM>>>(
        sh, sl, wihh1, wihl1, xg, TB_, D4_, D_, bih1, bhh1);
    lstm_layer_persist<<<128, 512, LSTM_SMEM>>>(
        h0h + BD, h0l + BD, whhh1, whhl1, c0 + BD, xg, sh, sl,
        out_hn + BD, out_cn + BD);

    // ---- attention + output head ----
    hgemm_nt<0><<<dim3(D_ / 128, TB_ / 128), 256, HG_SMEM>>>(
        sh, sl, winh, winl, q, TB_, D_, D_, nullptr, nullptr);
    attn_kernel<<<dim3(B_, T_), 256>>>(q, ctx, sh, sl, cath, catl, out_attn);
    hgemm_nt<2><<<dim3(D_ / 128, TB_ / 128), 256, HG_SMEM>>>(
        cath, catl, wouth, woutl, out, TB_, D_, 2 * D_, nullptr, nullptr);
}

// round 15
// speedup vs baseline: 1.0006x; 1.0006x over previous
#include <cuda_runtime.h>
#include <cuda_bf16.h>
#include <math.h>

#define T_ 32
#define B_ 64
#define S_ 64
#define D_ 1024
#define D4_ 4096
#define TB_ 2048
#define BD_ (B_ * D_)

// ---------------- scratch (device globals) ----------------
__device__ float g_xg[TB_ * D4_];
__device__ float g_q [TB_ * D_];

__device__ __align__(16) __nv_bfloat16 g_x0h[TB_ * D_], g_x0l[TB_ * D_];
__device__ __align__(16) __nv_bfloat16 g_sh [TB_ * D_], g_sl [TB_ * D_];
__device__ __align__(16) __nv_bfloat16 g_h0h[2 * BD_],  g_h0l[2 * BD_];
__device__ __align__(16) __nv_bfloat16 g_cath[TB_ * 2 * D_], g_catl[TB_ * 2 * D_];

__device__ __align__(16) __nv_bfloat16 g_whhh0[D4_ * D_], g_whhl0[D4_ * D_];
__device__ __align__(16) __nv_bfloat16 g_whhh1[D4_ * D_], g_whhl1[D4_ * D_];
__device__ __align__(16) __nv_bfloat16 g_wihh0[D4_ * D_], g_wihl0[D4_ * D_];
__device__ __align__(16) __nv_bfloat16 g_wihh1[D4_ * D_], g_wihl1[D4_ * D_];
__device__ __align__(16) __nv_bfloat16 g_winh[D_ * D_],   g_winl[D_ * D_];
__device__ __align__(16) __nv_bfloat16 g_wouth[D_ * 2 * D_], g_woutl[D_ * 2 * D_];

__device__ unsigned g_done;
__device__ unsigned g_flag[128];   // per-block completed-step counter

// ---------------- asm helpers ----------------
__device__ __forceinline__ void mma16816(float* d, const unsigned* a, const unsigned* b)
{
    asm volatile(
        "mma.sync.aligned.m16n8k16.row.col.f32.bf16.bf16.f32 "
        "{%0,%1,%2,%3}, {%4,%5,%6,%7}, {%8,%9}, {%0,%1,%2,%3};"
        : "+f"(d[0]), "+f"(d[1]), "+f"(d[2]), "+f"(d[3])
        : "r"(a[0]), "r"(a[1]), "r"(a[2]), "r"(a[3]),
          "r"(b[0]), "r"(b[1]));
}
__device__ __forceinline__ void ldsm_x4(unsigned* r, unsigned addr)
{
    asm volatile("ldmatrix.sync.aligned.m8n8.x4.shared.b16 {%0,%1,%2,%3}, [%4];"
                 : "=r"(r[0]), "=r"(r[1]), "=r"(r[2]), "=r"(r[3]) : "r"(addr));
}
__device__ __forceinline__ void ldsm_x2(unsigned* r, unsigned addr)
{
    asm volatile("ldmatrix.sync.aligned.m8n8.x2.shared.b16 {%0,%1}, [%2];"
                 : "=r"(r[0]), "=r"(r[1]) : "r"(addr));
}
__device__ __forceinline__ void cpa16(unsigned saddr, const void* g)
{
    asm volatile("cp.async.cg.shared.global [%0], [%1], 16;" :: "r"(saddr), "l"(g) : "memory");
}
__device__ __forceinline__ void cp_commit() { asm volatile("cp.async.commit_group;" ::: "memory"); }
__device__ __forceinline__ void cp_wait0()  { asm volatile("cp.async.wait_group 0;" ::: "memory"); }
__device__ __forceinline__ unsigned ld_acq(const unsigned* p)
{
    unsigned v;
    asm volatile("ld.acquire.gpu.global.u32 %0, [%1];" : "=r"(v) : "l"(p) : "memory");
    return v;
}

__device__ __forceinline__ void split_store4(float4 v,
                                             __nv_bfloat162* hp,
                                             __nv_bfloat162* lp)
{
    float hx = __bfloat162float(__float2bfloat16(v.x));
    float hy = __bfloat162float(__float2bfloat16(v.y));
    float hz = __bfloat162float(__float2bfloat16(v.z));
    float hw = __bfloat162float(__float2bfloat16(v.w));
    hp[0] = __nv_bfloat162(__float2bfloat16(hx), __float2bfloat16(hy));
    hp[1] = __nv_bfloat162(__float2bfloat16(hz), __float2bfloat16(hw));
    lp[0] = __nv_bfloat162(__float2bfloat16(v.x - hx), __float2bfloat16(v.y - hy));
    lp[1] = __nv_bfloat162(__float2bfloat16(v.z - hz), __float2bfloat16(v.w - hw));
}

// ---------------- fused split: all 6 weights + both h0 slices, one launch ---
#define RW  1048576
#define RWIN 262144
#define RWOUT 524288
#define RH 16384
#define FS_TOTAL (4 * RW + RWIN + RWOUT + 2 * RH)

__global__ __launch_bounds__(256)
void fused_split(const float* __restrict__ whh0, const float* __restrict__ wih0,
                 const float* __restrict__ whh1, const float* __restrict__ wih1,
                 const float* __restrict__ w_in, const float* __restrict__ w_out,
                 const float* __restrict__ h0,
                 __nv_bfloat16* whhh0, __nv_bfloat16* whhl0,
                 __nv_bfloat16* wihh0, __nv_bfloat16* wihl0,
                 __nv_bfloat16* whhh1, __nv_bfloat16* whhl1,
                 __nv_bfloat16* wihh1, __nv_bfloat16* wihl1,
                 __nv_bfloat16* winh,  __nv_bfloat16* winl,
                 __nv_bfloat16* wouth, __nv_bfloat16* woutl,
                 __nv_bfloat16* h0h,   __nv_bfloat16* h0l)
{
    long idx = (long)blockIdx.x * 256 + threadIdx.x;
    if (idx >= FS_TOTAL) return;
    const float* src;
    __nv_bfloat16 *hi, *lo;
    long l = idx;
    if (l < RW)                    { src = whh0; hi = whhh0; lo = whhl0; }
    else if ((l -= RW) < RW)       { src = wih0; hi = wihh0; lo = wihl0; }
    else if ((l -= RW) < RW)       { src = whh1; hi = whhh1; lo = whhl1; }
    else if ((l -= RW) < RW)       { src = wih1; hi = wihh1; lo = wihl1; }
    else if ((l -= RW) < RWIN)     { src = w_in; hi = winh;  lo = winl;  }
    else if ((l -= RWIN) < RWOUT)  { src = w_out; hi = wouth; lo = woutl; }
    else if ((l -= RWOUT) < 2 * RH){ src = h0;   hi = h0h;   lo = h0l;   }
    else return;
    float4 v = ((const float4*)src)[l];
    split_store4(v, (__nv_bfloat162*)hi + l * 2, (__nv_bfloat162*)lo + l * 2);
}

__global__ void embed_kernel(const int* __restrict__ tok,
                             const float* __restrict__ emb,
                             __nv_bfloat16* __restrict__ xh,
                             __nv_bfloat16* __restrict__ xl)
{
    int tb = blockIdx.x;
    int t4 = threadIdx.x;
    int tk = tok[tb];
    float4 v = make_float4(0.f, 0.f, 0.f, 0.f);
    if (tk != 0) v = ((const float4*)(emb + (size_t)tk * D_))[t4];
    split_store4(v, (__nv_bfloat162*)(xh + (size_t)tb * D_) + t4 * 2,
                    (__nv_bfloat162*)(xl + (size_t)tb * D_) + t4 * 2);
}

// ---------------- bf16 tensor GEMM: single-sweep 3-term compensation --------
#define HG_SMEM 65536
template<int EPI>
__global__ __launch_bounds__(256, 2)
void hgemm_nt(const __nv_bfloat16* __restrict__ Ahi,
              const __nv_bfloat16* __restrict__ Alo,
              const __nv_bfloat16* __restrict__ Bhi,
              const __nv_bfloat16* __restrict__ Blo,
              float* __restrict__ C, int M, int N, int K,
              const float* __restrict__ bias1, const float* __restrict__ bias2)
{
    extern __shared__ char hsm[];
    const unsigned SA = (unsigned)__cvta_generic_to_shared(hsm);
    const unsigned SB = SA + 32768;

    const int tid  = threadIdx.x;
    const int wid  = tid >> 5;
    const int lane = tid & 31;
    const int gid  = lane >> 2;
    const int tig  = lane & 3;
    const int wm   = wid >> 2;
    const int wn   = wid & 3;
    const int bm   = blockIdx.y * 128;
    const int bn   = blockIdx.x * 128;
    const int KC   = K >> 5;

    float acc[4][4][4];
#pragma unroll
    for (int mt = 0; mt < 4; mt++)
#pragma unroll
        for (int nt = 0; nt < 4; nt++)
#pragma unroll
            for (int r = 0; r < 4; r++) acc[mt][nt][r] = 0.f;

    auto issue = [&](int it) {
        int kc = it << 5;
        int buf = it & 1;
#pragma unroll
        for (int j = 0; j < 8; j++) {
            int id   = tid + (j << 8);
            int mat  = id >> 9;
            int e    = id & 511;
            int half = e & 1;
            int row  = (e >> 1) & 127;
            int kh   = e >> 8;
            const __nv_bfloat16* src =
                (mat == 0) ? Ahi : (mat == 1) ? Alo : (mat == 2) ? Bhi : Blo;
            int grow = ((mat < 2) ? bm : bn) + row;
            src += (size_t)grow * K + kc + (kh << 4) + (half << 3);
            unsigned dst = ((mat < 2) ? SA : SB) + (unsigned)(buf * 16384 +
                           (mat & 1) * 8192 + (kh << 12) + (row << 5) + (half << 4));
            cpa16(dst, src);
        }
        cp_commit();
    };

    const unsigned aoff = (unsigned)(((wm << 6) + (lane & 15)) * 32 + (((lane >> 4) & 1) << 4));
    const unsigned boff = (unsigned)(((wn << 5) + (lane & 7)) * 32 + (((lane >> 3) & 1) << 4));

    issue(0);
    for (int it = 0; it < KC; it++) {
        cp_wait0();
        __syncthreads();
        if (it + 1 < KC) issue(it + 1);
        const unsigned ba = SA + (unsigned)((it & 1) * 16384);
        const unsigned bb = SB + (unsigned)((it & 1) * 16384);
#pragma unroll
        for (int kh = 0; kh < 2; kh++) {
            unsigned ahi[4][4], alo[4][4];
#pragma unroll
            for (int mt = 0; mt < 4; mt++) {
                ldsm_x4(ahi[mt], ba + (kh << 12) + (unsigned)(mt << 9) + aoff);
                ldsm_x4(alo[mt], ba + 8192 + (kh << 12) + (unsigned)(mt << 9) + aoff);
            }
#pragma unroll
            for (int nt = 0; nt < 4; nt++) {
                unsigned bh[2], bl[2];
                ldsm_x2(bh, bb + (kh << 12) + (unsigned)(nt << 8) + boff);
                ldsm_x2(bl, bb + 8192 + (kh << 12) + (unsigned)(nt << 8) + boff);
#pragma unroll
                for (int mt = 0; mt < 4; mt++) {
                    mma16816(acc[mt][nt], ahi[mt], bh);
                    mma16816(acc[mt][nt], alo[mt], bh);
                    mma16816(acc[mt][nt], ahi[mt], bl);
                }
            }
        }
    }

#pragma unroll
    for (int mt = 0; mt < 4; mt++)
#pragma unroll
        for (int nt = 0; nt < 4; nt++)
#pragma unroll
            for (int rp = 0; rp < 2; rp++) {
                int row = bm + (wm << 6) + (mt << 4) + gid + (rp << 3);
                int col = bn + (wn << 5) + (nt << 3) + (tig << 1);
                float v0 = acc[mt][nt][rp * 2];
                float v1 = acc[mt][nt][rp * 2 + 1];
                if (EPI == 1) {
                    v0 += __ldg(bias1 + col) + __ldg(bias2 + col);
                    v1 += __ldg(bias1 + col + 1) + __ldg(bias2 + col + 1);
                }
                if (EPI == 2) { v0 = tanhf(v0); v1 = tanhf(v1); }
                float2 o; o.x = v0; o.y = v1;
                *(float2*)(C + (size_t)row * N + col) = o;
            }
}

// ---------------- persistent LSTM layer: producer-flag sync -----------------
// R13 structure (512 thr, 2-way k-split) but grid_bar replaced by per-block
// flags: staging chunk ck of step t waits only on the 16 producer blocks of
// those h columns (8 per k-half). Producers publish after their slice store.
#define LSTM_SMEM 215296

__global__ __launch_bounds__(512, 1)
void lstm_layer_persist(const __nv_bfloat16* __restrict__ h0h,
                        const __nv_bfloat16* __restrict__ h0l,
                        const __nv_bfloat16* __restrict__ whi,
                        const __nv_bfloat16* __restrict__ wlo,
                        const float* __restrict__ c0,
                        const float* __restrict__ xg,
                        __nv_bfloat16* __restrict__ shh,
                        __nv_bfloat16* __restrict__ shl,
                        float* __restrict__ hn_out,
                        float* __restrict__ cn_out)
{
    extern __shared__ char smem[];
    float* red2 = (float*)(smem + 196608);
    float* cs   = (float*)(smem + 212992);

    const int tid  = threadIdx.x;
    const int wid  = tid >> 5;
    const int lane = tid & 31;
    const int kh2  = wid >> 3;
    const int w8   = wid & 7;
    const int mt   = w8 & 3;
    const int nh   = w8 >> 2;
    const int d0   = blockIdx.x << 3;
    const int pb   = tid >> 3;
    const int pd   = tid & 7;

    const unsigned WS = (unsigned)__cvta_generic_to_shared(smem);
    const unsigned HS = WS + 131072;

#pragma unroll
    for (int i = 0; i < 16; i++) {
        int id   = tid + (i << 9);
        int half = id & 1;
        int r    = (id >> 1) & 31;
        int k16  = (id >> 6) & 63;
        int hl   = id >> 12;
        int grow = ((r >> 3) << 10) + d0 + (r & 7);
        const __nv_bfloat16* src =
            (hl ? wlo : whi) + (size_t)grow * D_ + (k16 << 4) + (half << 3);
        cpa16(WS + hl * 65536 + (k16 << 10) + (r << 5) + (half << 4), src);
    }
    cp_commit();
    cs[tid] = __ldg(c0 + (size_t)pb * D_ + d0 + pd);
    cp_wait0();
    __syncthreads();

    const unsigned aoff  = (unsigned)(((mt << 4) + (lane & 15)) * 32 + (((lane >> 4) & 1) << 4));
    const unsigned boff0 = (unsigned)(((nh << 4) + (lane & 7)) * 32 + (((lane >> 3) & 1) << 4));
    const unsigned boff1 = boff0 + 8 * 32;

    // pointwise inverse-mapping indices
    int pidx[4];
#pragma unroll
    for (int g = 0; g < 4; g++) {
        int n = (g << 3) + pd;
        int pmt = pb >> 4, pgid = pb & 7, prb = (pb >> 3) & 1;
        int pnh = n >> 4, pnt = (n >> 3) & 1, ptig = (n >> 1) & 3, prn = n & 1;
        int pw8 = (pnh << 2) | pmt;
        int pln = (pgid << 2) | ptig;
        int pr  = (prb << 1) | prn;
        pidx[g] = (pw8 << 8) + (pln << 3) + (pnt << 2) + pr;
    }

    for (int t = 0; t < T_; t++) {
        const __nv_bfloat16* ah = t ? shh + (size_t)(t - 1) * BD_ : h0h;
        const __nv_bfloat16* al = t ? shl + (size_t)(t - 1) * BD_ : h0l;
        const float* xgt = xg + (size_t)t * B_ * D4_;

        float xv[4];
#pragma unroll
        for (int g = 0; g < 4; g++)
            xv[g] = __ldg(xgt + (size_t)pb * D4_ + (g << 10) + d0 + pd);

        float acc[2][4];
#pragma unroll
        for (int nt = 0; nt < 2; nt++)
#pragma unroll
            for (int r = 0; r < 4; r++) acc[nt][r] = 0.f;

        // wait for the 16 producer blocks of staging group ii (skip at t=0)
        auto waitgrp = [&](int ii) {
            if (t == 0) return;
            if (tid < 16) {
                int p = (tid < 8) ? ((ii << 3) + tid) : (64 + (ii << 3) + (tid - 8));
                const unsigned* fp = &g_flag[p];
                while (ld_acq(fp) < (unsigned)t) { }
            }
        };

        auto issue = [&](int ii) {
            unsigned bA = (unsigned)((ii & 1) * 16384);
#pragma unroll
            for (int j = 0; j < 4; j++) {
                int id   = tid + (j << 9);
                int ch   = id >> 10;
                int e    = id & 1023;
                int half = e & 1;
                int row  = (e >> 1) & 63;
                int k16l = (e >> 7) & 3;
                int hl   = e >> 9;
                int ck   = (ch << 3) + ii;
                const __nv_bfloat16* src =
                    (hl ? al : ah) + (size_t)row * D_ + (ck << 6) + (k16l << 4) + (half << 3);
                cpa16(HS + (unsigned)(ch * 32768) + bA + (unsigned)(hl * 8192 + (k16l << 11) + (row << 5) + (half << 4)), src);
            }
            cp_commit();
        };

        waitgrp(0);
        __syncthreads();
        issue(0);
        for (int i = 0; i < 8; i++) {
            cp_wait0();
            if (i < 7) waitgrp(i + 1);
            __syncthreads();
            if (i < 7) issue(i + 1);
            const unsigned hb = HS + (unsigned)(kh2 * 32768 + (i & 1) * 16384);
#pragma unroll
            for (int k16l = 0; k16l < 4; k16l++) {
                unsigned ahi[4], alo[4], bh0[2], bh1[2], bl0[2], bl1[2];
                ldsm_x4(ahi, hb + (k16l << 11) + aoff);
                ldsm_x4(alo, hb + 8192 + (k16l << 11) + aoff);
                unsigned kb = WS + (unsigned)(((kh2 << 5) + (i << 2) + k16l) << 10);
                ldsm_x2(bh0, kb + boff0);
                ldsm_x2(bh1, kb + boff1);
                ldsm_x2(bl0, kb + 65536 + boff0);
                ldsm_x2(bl1, kb + 65536 + boff1);
                mma16816(acc[0], ahi, bh0);
                mma16816(acc[1], ahi, bh1);
                mma16816(acc[0], alo, bh0);
                mma16816(acc[1], alo, bh1);
                mma16816(acc[0], ahi, bl0);
                mma16816(acc[1], ahi, bl1);
            }
        }

        // store partials to this half's region
        {
            float4* r2 = (float4*)(red2 + (kh2 << 11));
            int base4 = ((w8 << 8) + (lane << 3)) >> 2;
            r2[base4]     = make_float4(acc[0][0], acc[0][1], acc[0][2], acc[0][3]);
            r2[base4 + 1] = make_float4(acc[1][0], acc[1][1], acc[1][2], acc[1][3]);
        }
        __syncthreads();

        // pointwise
        {
            float ig = red2[pidx[0]] + red2[2048 + pidx[0]] + xv[0];
            float fg = red2[pidx[1]] + red2[2048 + pidx[1]] + xv[1];
            float gg = red2[pidx[2]] + red2[2048 + pidx[2]] + xv[2];
            float og = red2[pidx[3]] + red2[2048 + pidx[3]] + xv[3];
            float ci = cs[tid];
            float i_ = 1.f / (1.f + __expf(-ig));
            float f_ = 1.f / (1.f + __expf(-fg));
            float o_ = 1.f / (1.f + __expf(-og));
            float cn = f_ * ci + i_ * tanhf(gg);
            float hn = o_ * tanhf(cn);
            cs[tid] = cn;
            size_t idx = (size_t)t * BD_ + (size_t)pb * D_ + d0 + pd;
            float hh = __bfloat162float(__float2bfloat16(hn));
            shh[idx] = __float2bfloat16(hh);
            shl[idx] = __float2bfloat16(hn - hh);
            if (t == T_ - 1) hn_out[(size_t)pb * D_ + d0 + pd] = hn;
        }

        // publish this block's step-t slice
        __syncthreads();
        if (tid == 0) {
            __threadfence();
            atomicExch(&g_flag[blockIdx.x], (unsigned)(t + 1));
        }
    }

    cn_out[(size_t)pb * D_ + d0 + pd] = cs[tid];

    // end handshake: last block resets flags for the next launch / replay
    __threadfence();
    __syncthreads();
    if (tid == 0) {
        unsigned d = atomicAdd(&g_done, 1u) + 1;
        if (d == gridDim.x) {
            for (int i = 0; i < 128; i++) g_flag[i] = 0;
            g_done = 0;
            __threadfence();
        }
    }
}

// ---------------- attention ----------------
__global__ __launch_bounds__(256)
void attn_kernel(const float* __restrict__ q,
                 const float* __restrict__ ctx,
                 const __nv_bfloat16* __restrict__ xh,
                 const __nv_bfloat16* __restrict__ xl,
                 __nv_bfloat16* __restrict__ cath,
                 __nv_bfloat16* __restrict__ catl,
                 float* __restrict__ attn_out)
{
    const int b = blockIdx.x;
    const int t = blockIdx.y;
    const int tb = t * B_ + b;
    __shared__ float qs[D_];
    __shared__ float sc[S_];

    const int tid = threadIdx.x;
    const int warp = tid >> 5, lane = tid & 31;

    ((float4*)qs)[tid] = ((const float4*)(q + (size_t)tb * D_))[tid];
    __syncthreads();

#pragma unroll
    for (int si = 0; si < 8; si++) {
        int s = warp * 8 + si;
        const float4* crow = (const float4*)(ctx + (size_t)(s * B_ + b) * D_);
        float sum = 0.f;
#pragma unroll
        for (int i = 0; i < 8; i++) {
            float4 cv = crow[lane + 32 * i];
            float4 qv = ((const float4*)qs)[lane + 32 * i];
            sum = fmaf(cv.x, qv.x, sum);
            sum = fmaf(cv.y, qv.y, sum);
            sum = fmaf(cv.z, qv.z, sum);
            sum = fmaf(cv.w, qv.w, sum);
        }
#pragma unroll
        for (int off = 16; off; off >>= 1)
            sum += __shfl_down_sync(0xffffffffu, sum, off);
        if (lane == 0) sc[s] = sum;
    }
    __syncthreads();

    if (warp == 0) {
        float v0 = sc[lane], v1 = sc[lane + 32];
        float m = fmaxf(v0, v1);
#pragma unroll
        for (int off = 16; off; off >>= 1)
            m = fmaxf(m, __shfl_xor_sync(0xffffffffu, m, off));
        float e0 = __expf(v0 - m), e1 = __expf(v1 - m);
        float ssum = e0 + e1;
#pragma unroll
        for (int off = 16; off; off >>= 1)
            ssum += __shfl_xor_sync(0xffffffffu, ssum, off);
        float inv = 1.f / ssum;
        sc[lane] = e0 * inv;
        sc[lane + 32] = e1 * inv;
    }
    __syncthreads();

    float4 accv = make_float4(0.f, 0.f, 0.f, 0.f);
    for (int s = 0; s < S_; s++) {
        float a = sc[s];
        float4 cv = ((const float4*)(ctx + (size_t)(s * B_ + b) * D_))[tid];
        accv.x = fmaf(a, cv.x, accv.x);
        accv.y = fmaf(a, cv.y, accv.y);
        accv.z = fmaf(a, cv.z, accv.z);
        accv.w = fmaf(a, cv.w, accv.w);
    }
    __nv_bfloat162* ch = (__nv_bfloat162*)(cath + (size_t)tb * 2 * D_);
    __nv_bfloat162* cl = (__nv_bfloat162*)(catl + (size_t)tb * 2 * D_);
    split_store4(accv, ch + tid * 2, cl + tid * 2);

    const unsigned* xhu = (const unsigned*)(xh + (size_t)tb * D_);
    const unsigned* xlu = (const unsigned*)(xl + (size_t)tb * D_);
    unsigned* chu = (unsigned*)(cath + (size_t)tb * 2 * D_ + D_);
    unsigned* clu = (unsigned*)(catl + (size_t)tb * 2 * D_ + D_);
    chu[tid] = xhu[tid]; chu[tid + 256] = xhu[tid + 256];
    clu[tid] = xlu[tid]; clu[tid + 256] = xlu[tid + 256];

    if (t == T_ - 1 && tid < S_) attn_out[b * S_ + tid] = sc[tid];
}

// ---------------- launch ----------------
extern "C" void kernel_launch(void* const* d_in, const int* in_sizes, int n_in,
                              void* d_out, int out_size)
{
    (void)in_sizes; (void)n_in; (void)out_size;

    const int*   input = (const int*)  d_in[0];
    const float* h0    = (const float*)d_in[1];
    const float* c0    = (const float*)d_in[2];
    const float* ctx   = (const float*)d_in[3];
    const float* emb   = (const float*)d_in[5];
    const float* wih0  = (const float*)d_in[6];
    const float* whh0  = (const float*)d_in[7];
    const float* bih0  = (const float*)d_in[8];
    const float* bhh0  = (const float*)d_in[9];
    const float* wih1  = (const float*)d_in[10];
    const float* whh1  = (const float*)d_in[11];
    const float* bih1  = (const float*)d_in[12];
    const float* bhh1  = (const float*)d_in[13];
    const float* w_in  = (const float*)d_in[14];
    const float* w_out = (const float*)d_in[15];

    float* out      = (float*)d_out;
    float* out_hn   = out + (size_t)TB_ * D_;
    float* out_cn   = out_hn + (size_t)2 * BD_;
    float* out_attn = out_cn + (size_t)2 * BD_;

    float *xg, *q;
    cudaGetSymbolAddress((void**)&xg, g_xg);
    cudaGetSymbolAddress((void**)&q,  g_q);

    __nv_bfloat16 *x0h, *x0l, *sh, *sl, *h0h, *h0l, *cath, *catl;
    __nv_bfloat16 *whhh0, *whhl0, *whhh1, *whhl1;
    __nv_bfloat16 *wihh0, *wihl0, *wihh1, *wihl1, *winh, *winl, *wouth, *woutl;
    cudaGetSymbolAddress((void**)&x0h, g_x0h);   cudaGetSymbolAddress((void**)&x0l, g_x0l);
    cudaGetSymbolAddress((void**)&sh,  g_sh);    cudaGetSymbolAddress((void**)&sl,  g_sl);
    cudaGetSymbolAddress((void**)&h0h, g_h0h);   cudaGetSymbolAddress((void**)&h0l, g_h0l);
    cudaGetSymbolAddress((void**)&cath, g_cath); cudaGetSymbolAddress((void**)&catl, g_catl);
    cudaGetSymbolAddress((void**)&whhh0, g_whhh0); cudaGetSymbolAddress((void**)&whhl0, g_whhl0);
    cudaGetSymbolAddress((void**)&whhh1, g_whhh1); cudaGetSymbolAddress((void**)&whhl1, g_whhl1);
    cudaGetSymbolAddress((void**)&wihh0, g_wihh0); cudaGetSymbolAddress((void**)&wihl0, g_wihl0);
    cudaGetSymbolAddress((void**)&wihh1, g_wihh1); cudaGetSymbolAddress((void**)&wihl1, g_wihl1);
    cudaGetSymbolAddress((void**)&winh,  g_winh);  cudaGetSymbolAddress((void**)&winl,  g_winl);
    cudaGetSymbolAddress((void**)&wouth, g_wouth); cudaGetSymbolAddress((void**)&woutl, g_woutl);

    static int smem_set = 0;
    if (!smem_set) {
        cudaFuncSetAttribute(lstm_layer_persist,
                             cudaFuncAttributeMaxDynamicSharedMemorySize, LSTM_SMEM);
        cudaFuncSetAttribute(hgemm_nt<0>,
                             cudaFuncAttributeMaxDynamicSharedMemorySize, HG_SMEM);
        cudaFuncSetAttribute(hgemm_nt<1>,
                             cudaFuncAttributeMaxDynamicSharedMemorySize, HG_SMEM);
        cudaFuncSetAttribute(hgemm_nt<2>,
                             cudaFuncAttributeMaxDynamicSharedMemorySize, HG_SMEM);
        smem_set = 1;
    }

    const size_t BD = (size_t)BD_;

    // ---- all splits in ONE launch ----
    fused_split<<<(FS_TOTAL + 255) / 256, 256>>>(
        whh0, wih0, whh1, wih1, w_in, w_out, h0,
        whhh0, whhl0, wihh0, wihl0, whhh1, whhl1, wihh1, wihl1,
        winh, winl, wouth, woutl, h0h, h0l);
    embed_kernel<<<TB_, 256>>>(input, emb, x0h, x0l);

    // ---- layer 0 ----
    hgemm_nt<1><<<dim3(D4_ / 128, TB_ / 128), 256, HG_SMEM>>>(
        x0h, x0l, wihh0, wihl0, xg, TB_, D4_, D_, bih0, bhh0);
    lstm_layer_persist<<<128, 512, LSTM_SMEM>>>(
        h0h, h0l, whhh0, whhl0, c0, xg, sh, sl, out_hn, out_cn);

    // ---- layer 1 ----
    hgemm_nt<1><<<dim3(D4_ / 128, TB_ / 128), 256, HG_SMEM>>>(
        sh, sl, wihh1, wihl1, xg, TB_, D4_, D_, bih1, bhh1);
    lstm_layer_persist<<<128, 512, LSTM_SMEM>>>(
        h0h + BD, h0l + BD, whhh1, whhl1, c0 + BD, xg, sh, sl,
        out_hn + BD, out_cn + BD);

    // ---- attention + output head ----
    hgemm_nt<0><<<dim3(D_ / 128, TB_ / 128), 256, HG_SMEM>>>(
        sh, sl, winh, winl, q, TB_, D_, D_, nullptr, nullptr);
    attn_kernel<<<dim3(B_, T_), 256>>>(q, ctx, sh, sl, cath, catl, out_attn);
    hgemm_nt<2><<<dim3(D_ / 128, TB_ / 128), 256, HG_SMEM>>>(
        cath, catl, wouth, woutl, out, TB_, D_, 2 * D_, nullptr, nullptr);
}

// round 16
// speedup vs baseline: 1.1029x; 1.1023x over previous
#include <cuda_runtime.h>
#include <cuda_bf16.h>
#include <math.h>

#define T_ 32
#define B_ 64
#define S_ 64
#define D_ 1024
#define D4_ 4096
#define TB_ 2048
#define BD_ (B_ * D_)

__device__ float g_xg[TB_ * D4_];
__device__ float g_q [TB_ * D_];

__device__ __align__(16) __nv_bfloat16 g_x0h[TB_ * D_], g_x0l[TB_ * D_];
__device__ __align__(16) __nv_bfloat16 g_sh [TB_ * D_], g_sl [TB_ * D_];
__device__ __align__(16) __nv_bfloat16 g_h0h[2 * BD_],  g_h0l[2 * BD_];
__device__ __align__(16) __nv_bfloat16 g_cath[TB_ * 2 * D_], g_catl[TB_ * 2 * D_];

__device__ __align__(16) __nv_bfloat16 g_whhh0[D4_ * D_], g_whhl0[D4_ * D_];
__device__ __align__(16) __nv_bfloat16 g_whhh1[D4_ * D_], g_whhl1[D4_ * D_];
__device__ __align__(16) __nv_bfloat16 g_wihh0[D4_ * D_], g_wihl0[D4_ * D_];
__device__ __align__(16) __nv_bfloat16 g_wihh1[D4_ * D_], g_wihl1[D4_ * D_];
__device__ __align__(16) __nv_bfloat16 g_winh[D_ * D_],   g_winl[D_ * D_];
__device__ __align__(16) __nv_bfloat16 g_wouth[D_ * 2 * D_], g_woutl[D_ * 2 * D_];

__device__ unsigned g_cnt;
__device__ unsigned g_done;

__device__ __forceinline__ void mma16816(float* d, const unsigned* a, const unsigned* b)
{
    asm volatile(
        "mma.sync.aligned.m16n8k16.row.col.f32.bf16.bf16.f32 "
        "{%0,%1,%2,%3}, {%4,%5,%6,%7}, {%8,%9}, {%0,%1,%2,%3};"
        : "+f"(d[0]), "+f"(d[1]), "+f"(d[2]), "+f"(d[3])
        : "r"(a[0]), "r"(a[1]), "r"(a[2]), "r"(a[3]),
          "r"(b[0]), "r"(b[1]));
}
__device__ __forceinline__ void ldsm_x4(unsigned* r, unsigned addr)
{
    asm volatile("ldmatrix.sync.aligned.m8n8.x4.shared.b16 {%0,%1,%2,%3}, [%4];"
                 : "=r"(r[0]), "=r"(r[1]), "=r"(r[2]), "=r"(r[3]) : "r"(addr));
}
__device__ __forceinline__ void ldsm_x2(unsigned* r, unsigned addr)
{
    asm volatile("ldmatrix.sync.aligned.m8n8.x2.shared.b16 {%0,%1}, [%2];"
                 : "=r"(r[0]), "=r"(r[1]) : "r"(addr));
}
__device__ __forceinline__ void cpa16(unsigned saddr, const void* g)
{
    asm volatile("cp.async.cg.shared.global [%0], [%1], 16;" :: "r"(saddr), "l"(g) : "memory");
}
__device__ __forceinline__ void cp_commit() { asm volatile("cp.async.commit_group;" ::: "memory"); }
__device__ __forceinline__ void cp_wait0()  { asm volatile("cp.async.wait_group 0;" ::: "memory"); }

__device__ __forceinline__ void split_store4(float4 v,
                                             __nv_bfloat162* hp,
                                             __nv_bfloat162* lp)
{
    float hx = __bfloat162float(__float2bfloat16(v.x));
    float hy = __bfloat162float(__float2bfloat16(v.y));
    float hz = __bfloat162float(__float2bfloat16(v.z));
    float hw = __bfloat162float(__float2bfloat16(v.w));
    hp[0] = __nv_bfloat162(__float2bfloat16(hx), __float2bfloat16(hy));
    hp[1] = __nv_bfloat162(__float2bfloat16(hz), __float2bfloat16(hw));
    lp[0] = __nv_bfloat162(__float2bfloat16(v.x - hx), __float2bfloat16(v.y - hy));
    lp[1] = __nv_bfloat162(__float2bfloat16(v.z - hz), __float2bfloat16(v.w - hw));
}

#define RW  1048576
#define RWIN 262144
#define RWOUT 524288
#define RH 16384
#define FS_TOTAL (4 * RW + RWIN + RWOUT + 2 * RH)

__global__ __launch_bounds__(256)
void fused_split(const float* __restrict__ whh0, const float* __restrict__ wih0,
                 const float* __restrict__ whh1, const float* __restrict__ wih1,
                 const float* __restrict__ w_in, const float* __restrict__ w_out,
                 const float* __restrict__ h0,
                 __nv_bfloat16* whhh0, __nv_bfloat16* whhl0,
                 __nv_bfloat16* wihh0, __nv_bfloat16* wihl0,
                 __nv_bfloat16* whhh1, __nv_bfloat16* whhl1,
                 __nv_bfloat16* wihh1, __nv_bfloat16* wihl1,
                 __nv_bfloat16* winh,  __nv_bfloat16* winl,
                 __nv_bfloat16* wouth, __nv_bfloat16* woutl,
                 __nv_bfloat16* h0h,   __nv_bfloat16* h0l)
{
    long idx = (long)blockIdx.x * 256 + threadIdx.x;
    if (idx >= FS_TOTAL) return;
    const float* src;
    __nv_bfloat16 *hi, *lo;
    long l = idx;
    if (l < RW)                    { src = whh0; hi = whhh0; lo = whhl0; }
    else if ((l -= RW) < RW)       { src = wih0; hi = wihh0; lo = wihl0; }
    else if ((l -= RW) < RW)       { src = whh1; hi = whhh1; lo = whhl1; }
    else if ((l -= RW) < RW)       { src = wih1; hi = wihh1; lo = wihl1; }
    else if ((l -= RW) < RWIN)     { src = w_in; hi = winh;  lo = winl;  }
    else if ((l -= RWIN) < RWOUT)  { src = w_out; hi = wouth; lo = woutl; }
    else if ((l -= RWOUT) < 2 * RH){ src = h0;   hi = h0h;   lo = h0l;   }
    else return;
    float4 v = ((const float4*)src)[l];
    split_store4(v, (__nv_bfloat162*)hi + l * 2, (__nv_bfloat162*)lo + l * 2);
}

__global__ void embed_kernel(const int* __restrict__ tok,
                             const float* __restrict__ emb,
                             __nv_bfloat16* __restrict__ xh,
                             __nv_bfloat16* __restrict__ xl)
{
    int tb = blockIdx.x;
    int t4 = threadIdx.x;
    int tk = tok[tb];
    float4 v = make_float4(0.f, 0.f, 0.f, 0.f);
    if (tk != 0) v = ((const float4*)(emb + (size_t)tk * D_))[t4];
    split_store4(v, (__nv_bfloat162*)(xh + (size_t)tb * D_) + t4 * 2,
                    (__nv_bfloat162*)(xl + (size_t)tb * D_) + t4 * 2);
}

// ---------------- bf16 tensor GEMM (R11/R13-proven) ----------------
#define HG_SMEM 65536
template<int EPI>
__global__ __launch_bounds__(256, 2)
void hgemm_nt(const __nv_bfloat16* __restrict__ Ahi,
              const __nv_bfloat16* __restrict__ Alo,
              const __nv_bfloat16* __restrict__ Bhi,
              const __nv_bfloat16* __restrict__ Blo,
              float* __restrict__ C, int M, int N, int K,
              const float* __restrict__ bias1, const float* __restrict__ bias2)
{
    extern __shared__ char hsm[];
    const unsigned SA = (unsigned)__cvta_generic_to_shared(hsm);
    const unsigned SB = SA + 32768;

    const int tid  = threadIdx.x;
    const int wid  = tid >> 5;
    const int lane = tid & 31;
    const int gid  = lane >> 2;
    const int tig  = lane & 3;
    const int wm   = wid >> 2;
    const int wn   = wid & 3;
    const int bm   = blockIdx.y * 128;
    const int bn   = blockIdx.x * 128;
    const int KC   = K >> 5;

    float acc[4][4][4];
#pragma unroll
    for (int mt = 0; mt < 4; mt++)
#pragma unroll
        for (int nt = 0; nt < 4; nt++)
#pragma unroll
            for (int r = 0; r < 4; r++) acc[mt][nt][r] = 0.f;

    auto issue = [&](int it) {
        int kc = it << 5;
        int buf = it & 1;
#pragma unroll
        for (int j = 0; j < 8; j++) {
            int id   = tid + (j << 8);
            int mat  = id >> 9;
            int e    = id & 511;
            int half = e & 1;
            int row  = (e >> 1) & 127;
            int kh   = e >> 8;
            const __nv_bfloat16* src =
                (mat == 0) ? Ahi : (mat == 1) ? Alo : (mat == 2) ? Bhi : Blo;
            int grow = ((mat < 2) ? bm : bn) + row;
            src += (size_t)grow * K + kc + (kh << 4) + (half << 3);
            unsigned dst = ((mat < 2) ? SA : SB) + (unsigned)(buf * 16384 +
                           (mat & 1) * 8192 + (kh << 12) + (row << 5) + (half << 4));
            cpa16(dst, src);
        }
        cp_commit();
    };

    const unsigned aoff = (unsigned)(((wm << 6) + (lane & 15)) * 32 + (((lane >> 4) & 1) << 4));
    const unsigned boff = (unsigned)(((wn << 5) + (lane & 7)) * 32 + (((lane >> 3) & 1) << 4));

    issue(0);
    for (int it = 0; it < KC; it++) {
        cp_wait0();
        __syncthreads();
        if (it + 1 < KC) issue(it + 1);
        const unsigned ba = SA + (unsigned)((it & 1) * 16384);
        const unsigned bb = SB + (unsigned)((it & 1) * 16384);
#pragma unroll
        for (int kh = 0; kh < 2; kh++) {
            unsigned ahi[4][4], alo[4][4];
#pragma unroll
            for (int mt = 0; mt < 4; mt++) {
                ldsm_x4(ahi[mt], ba + (kh << 12) + (unsigned)(mt << 9) + aoff);
                ldsm_x4(alo[mt], ba + 8192 + (kh << 12) + (unsigned)(mt << 9) + aoff);
            }
#pragma unroll
            for (int nt = 0; nt < 4; nt++) {
                unsigned bh[2], bl[2];
                ldsm_x2(bh, bb + (kh << 12) + (unsigned)(nt << 8) + boff);
                ldsm_x2(bl, bb + 8192 + (kh << 12) + (unsigned)(nt << 8) + boff);
#pragma unroll
                for (int mt = 0; mt < 4; mt++) {
                    mma16816(acc[mt][nt], ahi[mt], bh);
                    mma16816(acc[mt][nt], alo[mt], bh);
                    mma16816(acc[mt][nt], ahi[mt], bl);
                }
            }
        }
    }

#pragma unroll
    for (int mt = 0; mt < 4; mt++)
#pragma unroll
        for (int nt = 0; nt < 4; nt++)
#pragma unroll
            for (int rp = 0; rp < 2; rp++) {
                int row = bm + (wm << 6) + (mt << 4) + gid + (rp << 3);
                int col = bn + (wn << 5) + (nt << 3) + (tig << 1);
                float v0 = acc[mt][nt][rp * 2];
                float v1 = acc[mt][nt][rp * 2 + 1];
                if (EPI == 1) {
                    v0 += __ldg(bias1 + col) + __ldg(bias2 + col);
                    v1 += __ldg(bias1 + col + 1) + __ldg(bias2 + col + 1);
                }
                if (EPI == 2) { v0 = tanhf(v0); v1 = tanhf(v1); }
                float2 o; o.x = v0; o.y = v1;
                *(float2*)(C + (size_t)row * N + col) = o;
            }
}

// ---------------- persistent LSTM (R13 base, split-phase barrier) ----------
#define LSTM_SMEM 215296

__global__ __launch_bounds__(512, 1)
void lstm_layer_persist(const __nv_bfloat16* __restrict__ h0h,
                        const __nv_bfloat16* __restrict__ h0l,
                        const __nv_bfloat16* __restrict__ whi,
                        const __nv_bfloat16* __restrict__ wlo,
                        const float* __restrict__ c0,
                        const float* __restrict__ xg,
                        __nv_bfloat16* __restrict__ shh,
                        __nv_bfloat16* __restrict__ shl,
                        float* __restrict__ hn_out,
                        float* __restrict__ cn_out)
{
    extern __shared__ char smem[];
    float* red2 = (float*)(smem + 196608);

    const int tid  = threadIdx.x;
    const int wid  = tid >> 5;
    const int lane = tid & 31;
    const int kh2  = wid >> 3;
    const int w8   = wid & 7;
    const int mt   = w8 & 3;
    const int nh   = w8 >> 2;
    const int d0   = blockIdx.x << 3;
    const int pb   = tid >> 3;
    const int pd   = tid & 7;

    const unsigned WS = (unsigned)__cvta_generic_to_shared(smem);
    const unsigned HS = WS + 131072;

#pragma unroll
    for (int i = 0; i < 16; i++) {
        int id   = tid + (i << 9);
        int half = id & 1;
        int r    = (id >> 1) & 31;
        int k16  = (id >> 6) & 63;
        int hl   = id >> 12;
        int grow = ((r >> 3) << 10) + d0 + (r & 7);
        const __nv_bfloat16* src =
            (hl ? wlo : whi) + (size_t)grow * D_ + (k16 << 4) + (half << 3);
        cpa16(WS + hl * 65536 + (k16 << 10) + (r << 5) + (half << 4), src);
    }
    cp_commit();
    float creg = __ldg(c0 + (size_t)pb * D_ + d0 + pd);   // c in register
    cp_wait0();
    __syncthreads();

    const unsigned aoff  = (unsigned)(((mt << 4) + (lane & 15)) * 32 + (((lane >> 4) & 1) << 4));
    const unsigned boff0 = (unsigned)(((nh << 4) + (lane & 7)) * 32 + (((lane >> 3) & 1) << 4));
    const unsigned boff1 = boff0 + 8 * 32;

    int pidx[4];
#pragma unroll
    for (int g = 0; g < 4; g++) {
        int n = (g << 3) + pd;
        int pmt = pb >> 4, pgid = pb & 7, prb = (pb >> 3) & 1;
        int pnh = n >> 4, pnt = (n >> 3) & 1, ptig = (n >> 1) & 3, prn = n & 1;
        int pw8 = (pnh << 2) | pmt;
        int pln = (pgid << 2) | ptig;
        int pr  = (prb << 1) | prn;
        pidx[g] = (pw8 << 8) + (pln << 3) + (pnt << 2) + pr;
    }

    for (int t = 0; t < T_; t++) {
        const __nv_bfloat16* ah = t ? shh + (size_t)(t - 1) * BD_ : h0h;
        const __nv_bfloat16* al = t ? shl + (size_t)(t - 1) * BD_ : h0l;
        const float* xgt = xg + (size_t)t * B_ * D4_;

        // h-independent prefetch FIRST (overlaps barrier drain from prev step)
        float xv[4];
#pragma unroll
        for (int g = 0; g < 4; g++)
            xv[g] = __ldg(xgt + (size_t)pb * D4_ + (g << 10) + d0 + pd);

        // barrier WAIT phase: all blocks arrived for step t's h (arrive was at
        // end of previous iteration)
        if (t > 0) {
            if (tid == 0)
                while (*((volatile unsigned*)&g_cnt) < (unsigned)t * gridDim.x) { }
            __syncthreads();
        }

        float acc[2][4];
#pragma unroll
        for (int nt = 0; nt < 2; nt++)
#pragma unroll
            for (int r = 0; r < 4; r++) acc[nt][r] = 0.f;

        auto issue = [&](int ii) {
            unsigned bA = (unsigned)((ii & 1) * 16384);
#pragma unroll
            for (int j = 0; j < 4; j++) {
                int id   = tid + (j << 9);
                int ch   = id >> 10;
                int e    = id & 1023;
                int half = e & 1;
                int row  = (e >> 1) & 63;
                int k16l = (e >> 7) & 3;
                int hl   = e >> 9;
                int ck   = (ch << 3) + ii;
                const __nv_bfloat16* src =
                    (hl ? al : ah) + (size_t)row * D_ + (ck << 6) + (k16l << 4) + (half << 3);
                cpa16(HS + (unsigned)(ch * 32768) + bA + (unsigned)(hl * 8192 + (k16l << 11) + (row << 5) + (half << 4)), src);
            }
            cp_commit();
        };

        issue(0);
        for (int i = 0; i < 8; i++) {
            cp_wait0();
            __syncthreads();
            if (i < 7) issue(i + 1);
            const unsigned hb = HS + (unsigned)(kh2 * 32768 + (i & 1) * 16384);
#pragma unroll
            for (int k16l = 0; k16l < 4; k16l++) {
                unsigned ahi[4], alo[4], bh0[2], bh1[2], bl0[2], bl1[2];
                ldsm_x4(ahi, hb + (k16l << 11) + aoff);
                ldsm_x4(alo, hb + 8192 + (k16l << 11) + aoff);
                unsigned kb = WS + (unsigned)(((kh2 << 5) + (i << 2) + k16l) << 10);
                ldsm_x2(bh0, kb + boff0);
                ldsm_x2(bh1, kb + boff1);
                ldsm_x2(bl0, kb + 65536 + boff0);
                ldsm_x2(bl1, kb + 65536 + boff1);
                mma16816(acc[0], ahi, bh0);
                mma16816(acc[1], ahi, bh1);
                mma16816(acc[0], alo, bh0);
                mma16816(acc[1], alo, bh1);
                mma16816(acc[0], ahi, bl0);
                mma16816(acc[1], ahi, bl1);
            }
        }

        {
            float4* r2 = (float4*)(red2 + (kh2 << 11));
            int base4 = ((w8 << 8) + (lane << 3)) >> 2;
            r2[base4]     = make_float4(acc[0][0], acc[0][1], acc[0][2], acc[0][3]);
            r2[base4 + 1] = make_float4(acc[1][0], acc[1][1], acc[1][2], acc[1][3]);
        }
        __syncthreads();

        {
            float ig = red2[pidx[0]] + red2[2048 + pidx[0]] + xv[0];
            float fg = red2[pidx[1]] + red2[2048 + pidx[1]] + xv[1];
            float gg = red2[pidx[2]] + red2[2048 + pidx[2]] + xv[2];
            float og = red2[pidx[3]] + red2[2048 + pidx[3]] + xv[3];
            float i_ = 1.f / (1.f + __expf(-ig));
            float f_ = 1.f / (1.f + __expf(-fg));
            float o_ = 1.f / (1.f + __expf(-og));
            float cn = f_ * creg + i_ * tanhf(gg);
            float hn = o_ * tanhf(cn);
            creg = cn;
            size_t idx = (size_t)t * BD_ + (size_t)pb * D_ + d0 + pd;
            float hh = __bfloat162float(__float2bfloat16(hn));
            shh[idx] = __float2bfloat16(hh);
            shl[idx] = __float2bfloat16(hn - hh);
            if (t == T_ - 1) hn_out[(size_t)pb * D_ + d0 + pd] = hn;
        }

        // barrier ARRIVE phase: publish step t completion, don't wait yet
        if (t < T_ - 1) {
            __threadfence();
            __syncthreads();
            if (tid == 0) atomicAdd(&g_cnt, 1u);
        }
    }

    cn_out[(size_t)pb * D_ + d0 + pd] = creg;

    __threadfence();
    __syncthreads();
    if (tid == 0) {
        unsigned d = atomicAdd(&g_done, 1u) + 1;
        if (d == gridDim.x) {
            g_cnt = 0;
            g_done = 0;
            __threadfence();
        }
    }
}

// ---------------- attention ----------------
__global__ __launch_bounds__(256)
void attn_kernel(const float* __restrict__ q,
                 const float* __restrict__ ctx,
                 const __nv_bfloat16* __restrict__ xh,
                 const __nv_bfloat16* __restrict__ xl,
                 __nv_bfloat16* __restrict__ cath,
                 __nv_bfloat16* __restrict__ catl,
                 float* __restrict__ attn_out)
{
    const int b = blockIdx.x;
    const int t = blockIdx.y;
    const int tb = t * B_ + b;
    __shared__ float qs[D_];
    __shared__ float sc[S_];

    const int tid = threadIdx.x;
    const int warp = tid >> 5, lane = tid & 31;

    ((float4*)qs)[tid] = ((const float4*)(q + (size_t)tb * D_))[tid];
    __syncthreads();

#pragma unroll
    for (int si = 0; si < 8; si++) {
        int s = warp * 8 + si;
        const float4* crow = (const float4*)(ctx + (size_t)(s * B_ + b) * D_);
        float sum = 0.f;
#pragma unroll
        for (int i = 0; i < 8; i++) {
            float4 cv = crow[lane + 32 * i];
            float4 qv = ((const float4*)qs)[lane + 32 * i];
            sum = fmaf(cv.x, qv.x, sum);
            sum = fmaf(cv.y, qv.y, sum);
            sum = fmaf(cv.z, qv.z, sum);
            sum = fmaf(cv.w, qv.w, sum);
        }
#pragma unroll
        for (int off = 16; off; off >>= 1)
            sum += __shfl_down_sync(0xffffffffu, sum, off);
        if (lane == 0) sc[s] = sum;
    }
    __syncthreads();

    if (warp == 0) {
        float v0 = sc[lane], v1 = sc[lane + 32];
        float m = fmaxf(v0, v1);
#pragma unroll
        for (int off = 16; off; off >>= 1)
            m = fmaxf(m, __shfl_xor_sync(0xffffffffu, m, off));
        float e0 = __expf(v0 - m), e1 = __expf(v1 - m);
        float ssum = e0 + e1;
#pragma unroll
        for (int off = 16; off; off >>= 1)
            ssum += __shfl_xor_sync(0xffffffffu, ssum, off);
        float inv = 1.f / ssum;
        sc[lane] = e0 * inv;
        sc[lane + 32] = e1 * inv;
    }
    __syncthreads();

    float4 accv = make_float4(0.f, 0.f, 0.f, 0.f);
    for (int s = 0; s < S_; s++) {
        float a = sc[s];
        float4 cv = ((const float4*)(ctx + (size_t)(s * B_ + b) * D_))[tid];
        accv.x = fmaf(a, cv.x, accv.x);
        accv.y = fmaf(a, cv.y, accv.y);
        accv.z = fmaf(a, cv.z, accv.z);
        accv.w = fmaf(a, cv.w, accv.w);
    }
    __nv_bfloat162* ch = (__nv_bfloat162*)(cath + (size_t)tb * 2 * D_);
    __nv_bfloat162* cl = (__nv_bfloat162*)(catl + (size_t)tb * 2 * D_);
    split_store4(accv, ch + tid * 2, cl + tid * 2);

    const unsigned* xhu = (const unsigned*)(xh + (size_t)tb * D_);
    const unsigned* xlu = (const unsigned*)(xl + (size_t)tb * D_);
    unsigned* chu = (unsigned*)(cath + (size_t)tb * 2 * D_ + D_);
    unsigned* clu = (unsigned*)(catl + (size_t)tb * 2 * D_ + D_);
    chu[tid] = xhu[tid]; chu[tid + 256] = xhu[tid + 256];
    clu[tid] = xlu[tid]; clu[tid + 256] = xlu[tid + 256];

    if (t == T_ - 1 && tid < S_) attn_out[b * S_ + tid] = sc[tid];
}

// ---------------- launch ----------------
extern "C" void kernel_launch(void* const* d_in, const int* in_sizes, int n_in,
                              void* d_out, int out_size)
{
    (void)in_sizes; (void)n_in; (void)out_size;

    const int*   input = (const int*)  d_in[0];
    const float* h0    = (const float*)d_in[1];
    const float* c0    = (const float*)d_in[2];
    const float* ctx   = (const float*)d_in[3];
    const float* emb   = (const float*)d_in[5];
    const float* wih0  = (const float*)d_in[6];
    const float* whh0  = (const float*)d_in[7];
    const float* bih0  = (const float*)d_in[8];
    const float* bhh0  = (const float*)d_in[9];
    const float* wih1  = (const float*)d_in[10];
    const float* whh1  = (const float*)d_in[11];
    const float* bih1  = (const float*)d_in[12];
    const float* bhh1  = (const float*)d_in[13];
    const float* w_in  = (const float*)d_in[14];
    const float* w_out = (const float*)d_in[15];

    float* out      = (float*)d_out;
    float* out_hn   = out + (size_t)TB_ * D_;
    float* out_cn   = out_hn + (size_t)2 * BD_;
    float* out_attn = out_cn + (size_t)2 * BD_;

    float *xg, *q;
    cudaGetSymbolAddress((void**)&xg, g_xg);
    cudaGetSymbolAddress((void**)&q,  g_q);

    __nv_bfloat16 *x0h, *x0l, *sh, *sl, *h0h, *h0l, *cath, *catl;
    __nv_bfloat16 *whhh0, *whhl0, *whhh1, *whhl1;
    __nv_bfloat16 *wihh0, *wihl0, *wihh1, *wihl1, *winh, *winl, *wouth, *woutl;
    cudaGetSymbolAddress((void**)&x0h, g_x0h);   cudaGetSymbolAddress((void**)&x0l, g_x0l);
    cudaGetSymbolAddress((void**)&sh,  g_sh);    cudaGetSymbolAddress((void**)&sl,  g_sl);
    cudaGetSymbolAddress((void**)&h0h, g_h0h);   cudaGetSymbolAddress((void**)&h0l, g_h0l);
    cudaGetSymbolAddress((void**)&cath, g_cath); cudaGetSymbolAddress((void**)&catl, g_catl);
    cudaGetSymbolAddress((void**)&whhh0, g_whhh0); cudaGetSymbolAddress((void**)&whhl0, g_whhl0);
    cudaGetSymbolAddress((void**)&whhh1, g_whhh1); cudaGetSymbolAddress((void**)&whhl1, g_whhl1);
    cudaGetSymbolAddress((void**)&wihh0, g_wihh0); cudaGetSymbolAddress((void**)&wihl0, g_wihl0);
    cudaGetSymbolAddress((void**)&wihh1, g_wihh1); cudaGetSymbolAddress((void**)&wihl1, g_wihl1);
    cudaGetSymbolAddress((void**)&winh,  g_winh);  cudaGetSymbolAddress((void**)&winl,  g_winl);
    cudaGetSymbolAddress((void**)&wouth, g_wouth); cudaGetSymbolAddress((void**)&woutl, g_woutl);

    static int smem_set = 0;
    if (!smem_set) {
        cudaFuncSetAttribute(lstm_layer_persist,
                             cudaFuncAttributeMaxDynamicSharedMemorySize, LSTM_SMEM);
        cudaFuncSetAttribute(hgemm_nt<0>,
                             cudaFuncAttributeMaxDynamicSharedMemorySize, HG_SMEM);
        cudaFuncSetAttribute(hgemm_nt<1>,
                             cudaFuncAttributeMaxDynamicSharedMemorySize, HG_SMEM);
        cudaFuncSetAttribute(hgemm_nt<2>,
                             cudaFuncAttributeMaxDynamicSharedMemorySize, HG_SMEM);
        smem_set = 1;
    }

    const size_t BD = (size_t)BD_;

    fused_split<<<(FS_TOTAL + 255) / 256, 256>>>(
        whh0, wih0, whh1, wih1, w_in, w_out, h0,
        whhh0, whhl0, wihh0, wihl0, whhh1, whhl1, wihh1, wihl1,
        winh, winl, wouth, woutl, h0h, h0l);
    embed_kernel<<<TB_, 256>>>(input, emb, x0h, x0l);

    hgemm_nt<1><<<dim3(D4_ / 128, TB_ / 128), 256, HG_SMEM>>>(
        x0h, x0l, wihh0, wihl0, xg, TB_, D4_, D_, bih0, bhh0);
    lstm_layer_persist<<<128, 512, LSTM_SMEM>>>(
        h0h, h0l, whhh0, whhl0, c0, xg, sh, sl, out_hn, out_cn);

    hgemm_nt<1><<<dim3(D4_ / 128, TB_ / 128), 256, HG_SMEM>>>(
        sh, sl, wihh1, wihl1, xg, TB_, D4_, D_, bih1, bhh1);
    lstm_layer_persist<<<128, 512, LSTM_SMEM>>>(
        h0h + BD, h0l + BD, whhh1, whhl1, c0 + BD, xg, sh, sl,
        out_hn + BD, out_cn + BD);

    hgemm_nt<0><<<dim3(D_ / 128, TB_ / 128), 256, HG_SMEM>>>(
        sh, sl, winh, winl, q, TB_, D_, D_, nullptr, nullptr);
    attn_kernel<<<dim3(B_, T_), 256>>>(q, ctx, sh, sl, cath, catl, out_attn);
    hgemm_nt<2><<<dim3(D_ / 128, TB_ / 128), 256, HG_SMEM>>>(
        cath, catl, wouth, woutl, out, TB_, D_, 2 * D_, nullptr, nullptr);
}

// round 17
// speedup vs baseline: 1.3047x; 1.1829x over previous
#include <cuda_runtime.h>
#include <cuda_bf16.h>
#include <cuda_fp16.h>
#include <math.h>

#define T_ 32
#define B_ 64
#define S_ 64
#define D_ 1024
#define D4_ 4096
#define TB_ 2048
#define BD_ (B_ * D_)

__device__ float g_xg[TB_ * D4_];
__device__ float g_q [TB_ * D_];

__device__ __align__(16) __nv_bfloat16 g_x0h[TB_ * D_], g_x0l[TB_ * D_];
__device__ __align__(16) __nv_bfloat16 g_sh [TB_ * D_], g_sl [TB_ * D_];
__device__ __align__(16) __half        g_sf [TB_ * D_];     // fp16 h sequence
__device__ __align__(16) __half        g_h0f[2 * BD_];
__device__ __align__(16) __nv_bfloat16 g_cath[TB_ * 2 * D_], g_catl[TB_ * 2 * D_];

__device__ __align__(16) __half        g_whhh0[D4_ * D_], g_whhl0[D4_ * D_];
__device__ __align__(16) __half        g_whhh1[D4_ * D_], g_whhl1[D4_ * D_];
__device__ __align__(16) __nv_bfloat16 g_wihh0[D4_ * D_], g_wihl0[D4_ * D_];
__device__ __align__(16) __nv_bfloat16 g_wihh1[D4_ * D_], g_wihl1[D4_ * D_];
__device__ __align__(16) __nv_bfloat16 g_winh[D_ * D_],   g_winl[D_ * D_];
__device__ __align__(16) __nv_bfloat16 g_wouth[D_ * 2 * D_], g_woutl[D_ * 2 * D_];

__device__ unsigned g_cnt;
__device__ unsigned g_done;

__device__ __forceinline__ void mma16816(float* d, const unsigned* a, const unsigned* b)
{
    asm volatile(
        "mma.sync.aligned.m16n8k16.row.col.f32.bf16.bf16.f32 "
        "{%0,%1,%2,%3}, {%4,%5,%6,%7}, {%8,%9}, {%0,%1,%2,%3};"
        : "+f"(d[0]), "+f"(d[1]), "+f"(d[2]), "+f"(d[3])
        : "r"(a[0]), "r"(a[1]), "r"(a[2]), "r"(a[3]), "r"(b[0]), "r"(b[1]));
}
__device__ __forceinline__ void mma16816h(float* d, const unsigned* a, const unsigned* b)
{
    asm volatile(
        "mma.sync.aligned.m16n8k16.row.col.f32.f16.f16.f32 "
        "{%0,%1,%2,%3}, {%4,%5,%6,%7}, {%8,%9}, {%0,%1,%2,%3};"
        : "+f"(d[0]), "+f"(d[1]), "+f"(d[2]), "+f"(d[3])
        : "r"(a[0]), "r"(a[1]), "r"(a[2]), "r"(a[3]), "r"(b[0]), "r"(b[1]));
}
__device__ __forceinline__ void ldsm_x4(unsigned* r, unsigned addr)
{
    asm volatile("ldmatrix.sync.aligned.m8n8.x4.shared.b16 {%0,%1,%2,%3}, [%4];"
                 : "=r"(r[0]), "=r"(r[1]), "=r"(r[2]), "=r"(r[3]) : "r"(addr));
}
__device__ __forceinline__ void ldsm_x2(unsigned* r, unsigned addr)
{
    asm volatile("ldmatrix.sync.aligned.m8n8.x2.shared.b16 {%0,%1}, [%2];"
                 : "=r"(r[0]), "=r"(r[1]) : "r"(addr));
}
__device__ __forceinline__ void cpa16(unsigned saddr, const void* g)
{
    asm volatile("cp.async.cg.shared.global [%0], [%1], 16;" :: "r"(saddr), "l"(g) : "memory");
}
__device__ __forceinline__ void cp_commit() { asm volatile("cp.async.commit_group;" ::: "memory"); }
__device__ __forceinline__ void cp_wait0()  { asm volatile("cp.async.wait_group 0;" ::: "memory"); }

__device__ __forceinline__ void split_store4(float4 v,
                                             __nv_bfloat162* hp, __nv_bfloat162* lp)
{
    float hx = __bfloat162float(__float2bfloat16(v.x));
    float hy = __bfloat162float(__float2bfloat16(v.y));
    float hz = __bfloat162float(__float2bfloat16(v.z));
    float hw = __bfloat162float(__float2bfloat16(v.w));
    hp[0] = __nv_bfloat162(__float2bfloat16(hx), __float2bfloat16(hy));
    hp[1] = __nv_bfloat162(__float2bfloat16(hz), __float2bfloat16(hw));
    lp[0] = __nv_bfloat162(__float2bfloat16(v.x - hx), __float2bfloat16(v.y - hy));
    lp[1] = __nv_bfloat162(__float2bfloat16(v.z - hz), __float2bfloat16(v.w - hw));
}
__device__ __forceinline__ void split_store4_h(float4 v, __half2* hp, __half2* lp)
{
    __half hx = __float2half_rn(v.x), hy = __float2half_rn(v.y);
    __half hz = __float2half_rn(v.z), hw = __float2half_rn(v.w);
    hp[0] = __half2(hx, hy); hp[1] = __half2(hz, hw);
    lp[0] = __half2(__float2half_rn(v.x - __half2float(hx)),
                    __float2half_rn(v.y - __half2float(hy)));
    lp[1] = __half2(__float2half_rn(v.z - __half2float(hz)),
                    __float2half_rn(v.w - __half2float(hw)));
}

#define RW  1048576
#define RWIN 262144
#define RWOUT 524288
#define RH 16384
#define FS_TOTAL (4 * RW + RWIN + RWOUT + 2 * RH)

__global__ __launch_bounds__(256)
void fused_split(const float* __restrict__ whh0, const float* __restrict__ wih0,
                 const float* __restrict__ whh1, const float* __restrict__ wih1,
                 const float* __restrict__ w_in, const float* __restrict__ w_out,
                 const float* __restrict__ h0,
                 __half* whhh0, __half* whhl0,
                 __nv_bfloat16* wihh0, __nv_bfloat16* wihl0,
                 __half* whhh1, __half* whhl1,
                 __nv_bfloat16* wihh1, __nv_bfloat16* wihl1,
                 __nv_bfloat16* winh,  __nv_bfloat16* winl,
                 __nv_bfloat16* wouth, __nv_bfloat16* woutl,
                 __half* h0f)
{
    long idx = (long)blockIdx.x * 256 + threadIdx.x;
    if (idx >= FS_TOTAL) return;
    long l = idx;
    if (l < RW) {                                   // whh0 -> fp16 hi/lo
        float4 v = ((const float4*)whh0)[l];
        split_store4_h(v, (__half2*)whhh0 + l * 2, (__half2*)whhl0 + l * 2);
        return;
    }
    if ((l -= RW) < RW) {
        float4 v = ((const float4*)wih0)[l];
        split_store4(v, (__nv_bfloat162*)wihh0 + l * 2, (__nv_bfloat162*)wihl0 + l * 2);
        return;
    }
    if ((l -= RW) < RW) {                           // whh1 -> fp16 hi/lo
        float4 v = ((const float4*)whh1)[l];
        split_store4_h(v, (__half2*)whhh1 + l * 2, (__half2*)whhl1 + l * 2);
        return;
    }
    if ((l -= RW) < RW) {
        float4 v = ((const float4*)wih1)[l];
        split_store4(v, (__nv_bfloat162*)wihh1 + l * 2, (__nv_bfloat162*)wihl1 + l * 2);
        return;
    }
    if ((l -= RW) < RWIN) {
        float4 v = ((const float4*)w_in)[l];
        split_store4(v, (__nv_bfloat162*)winh + l * 2, (__nv_bfloat162*)winl + l * 2);
        return;
    }
    if ((l -= RWIN) < RWOUT) {
        float4 v = ((const float4*)w_out)[l];
        split_store4(v, (__nv_bfloat162*)wouth + l * 2, (__nv_bfloat162*)woutl + l * 2);
        return;
    }
    if ((l -= RWOUT) < 2 * RH) {                    // h0 -> plain fp16
        float4 v = ((const float4*)h0)[l];
        ((__half2*)h0f)[l * 2]     = __floats2half2_rn(v.x, v.y);
        ((__half2*)h0f)[l * 2 + 1] = __floats2half2_rn(v.z, v.w);
    }
}

__global__ void embed_kernel(const int* __restrict__ tok,
                             const float* __restrict__ emb,
                             __nv_bfloat16* __restrict__ xh,
                             __nv_bfloat16* __restrict__ xl)
{
    int tb = blockIdx.x;
    int t4 = threadIdx.x;
    int tk = tok[tb];
    float4 v = make_float4(0.f, 0.f, 0.f, 0.f);
    if (tk != 0) v = ((const float4*)(emb + (size_t)tk * D_))[t4];
    split_store4(v, (__nv_bfloat162*)(xh + (size_t)tb * D_) + t4 * 2,
                    (__nv_bfloat162*)(xl + (size_t)tb * D_) + t4 * 2);
}

// ---------------- bf16 tensor GEMM (proven) ----------------
#define HG_SMEM 65536
template<int EPI>
__global__ __launch_bounds__(256, 2)
void hgemm_nt(const __nv_bfloat16* __restrict__ Ahi,
              const __nv_bfloat16* __restrict__ Alo,
              const __nv_bfloat16* __restrict__ Bhi,
              const __nv_bfloat16* __restrict__ Blo,
              float* __restrict__ C, int M, int N, int K,
              const float* __restrict__ bias1, const float* __restrict__ bias2)
{
    extern __shared__ char hsm[];
    const unsigned SA = (unsigned)__cvta_generic_to_shared(hsm);
    const unsigned SB = SA + 32768;

    const int tid  = threadIdx.x;
    const int wid  = tid >> 5;
    const int lane = tid & 31;
    const int gid  = lane >> 2;
    const int tig  = lane & 3;
    const int wm   = wid >> 2;
    const int wn   = wid & 3;
    const int bm   = blockIdx.y * 128;
    const int bn   = blockIdx.x * 128;
    const int KC   = K >> 5;

    float acc[4][4][4];
#pragma unroll
    for (int mt = 0; mt < 4; mt++)
#pragma unroll
        for (int nt = 0; nt < 4; nt++)
#pragma unroll
            for (int r = 0; r < 4; r++) acc[mt][nt][r] = 0.f;

    auto issue = [&](int it) {
        int kc = it << 5;
        int buf = it & 1;
#pragma unroll
        for (int j = 0; j < 8; j++) {
            int id   = tid + (j << 8);
            int mat  = id >> 9;
            int e    = id & 511;
            int half = e & 1;
            int row  = (e >> 1) & 127;
            int kh   = e >> 8;
            const __nv_bfloat16* src =
                (mat == 0) ? Ahi : (mat == 1) ? Alo : (mat == 2) ? Bhi : Blo;
            int grow = ((mat < 2) ? bm : bn) + row;
            src += (size_t)grow * K + kc + (kh << 4) + (half << 3);
            unsigned dst = ((mat < 2) ? SA : SB) + (unsigned)(buf * 16384 +
                           (mat & 1) * 8192 + (kh << 12) + (row << 5) + (half << 4));
            cpa16(dst, src);
        }
        cp_commit();
    };

    const unsigned aoff = (unsigned)(((wm << 6) + (lane & 15)) * 32 + (((lane >> 4) & 1) << 4));
    const unsigned boff = (unsigned)(((wn << 5) + (lane & 7)) * 32 + (((lane >> 3) & 1) << 4));

    issue(0);
    for (int it = 0; it < KC; it++) {
        cp_wait0();
        __syncthreads();
        if (it + 1 < KC) issue(it + 1);
        const unsigned ba = SA + (unsigned)((it & 1) * 16384);
        const unsigned bb = SB + (unsigned)((it & 1) * 16384);
#pragma unroll
        for (int kh = 0; kh < 2; kh++) {
            unsigned ahi[4][4], alo[4][4];
#pragma unroll
            for (int mt = 0; mt < 4; mt++) {
                ldsm_x4(ahi[mt], ba + (kh << 12) + (unsigned)(mt << 9) + aoff);
                ldsm_x4(alo[mt], ba + 8192 + (kh << 12) + (unsigned)(mt << 9) + aoff);
            }
#pragma unroll
            for (int nt = 0; nt < 4; nt++) {
                unsigned bh[2], bl[2];
                ldsm_x2(bh, bb + (kh << 12) + (unsigned)(nt << 8) + boff);
                ldsm_x2(bl, bb + 8192 + (kh << 12) + (unsigned)(nt << 8) + boff);
#pragma unroll
                for (int mt = 0; mt < 4; mt++) {
                    mma16816(acc[mt][nt], ahi[mt], bh);
                    mma16816(acc[mt][nt], alo[mt], bh);
                    mma16816(acc[mt][nt], ahi[mt], bl);
                }
            }
        }
    }

#pragma unroll
    for (int mt = 0; mt < 4; mt++)
#pragma unroll
        for (int nt = 0; nt < 4; nt++)
#pragma unroll
            for (int rp = 0; rp < 2; rp++) {
                int row = bm + (wm << 6) + (mt << 4) + gid + (rp << 3);
                int col = bn + (wn << 5) + (nt << 3) + (tig << 1);
                float v0 = acc[mt][nt][rp * 2];
                float v1 = acc[mt][nt][rp * 2 + 1];
                if (EPI == 1) {
                    v0 += __ldg(bias1 + col) + __ldg(bias2 + col);
                    v1 += __ldg(bias1 + col + 1) + __ldg(bias2 + col + 1);
                }
                if (EPI == 2) { v0 = tanhf(v0); v1 = tanhf(v1); }
                float2 o; o.x = v0; o.y = v1;
                *(float2*)(C + (size_t)row * N + col) = o;
            }
}

// ---------------- persistent LSTM: fp16 h (plain) x fp16 w (hi/lo) ---------
// smem: W 131072 | hs 2ch x 2buf x 8KB = 32768 | red2 16384  = 180224
#define LSTM_SMEM 180224

__global__ __launch_bounds__(512, 1)
void lstm_layer_persist(const __half* __restrict__ h0f,
                        const __half* __restrict__ whi,
                        const __half* __restrict__ wlo,
                        const float* __restrict__ c0,
                        const float* __restrict__ xg,
                        __nv_bfloat16* __restrict__ shh,
                        __nv_bfloat16* __restrict__ shl,
                        __half* __restrict__ sfh,
                        float* __restrict__ hn_out,
                        float* __restrict__ cn_out)
{
    extern __shared__ char smem[];
    float* red2 = (float*)(smem + 163840);

    const int tid  = threadIdx.x;
    const int wid  = tid >> 5;
    const int lane = tid & 31;
    const int kh2  = wid >> 3;
    const int w8   = wid & 7;
    const int mt   = w8 & 3;
    const int nh   = w8 >> 2;
    const int d0   = blockIdx.x << 3;
    const int pb   = tid >> 3;
    const int pd   = tid & 7;

    const unsigned WS = (unsigned)__cvta_generic_to_shared(smem);
    const unsigned HS = WS + 131072;

    // weight preload (fp16 hi/lo): [hl][k16 0..63][r 0..31][16 halves]
#pragma unroll
    for (int i = 0; i < 16; i++) {
        int id   = tid + (i << 9);
        int half = id & 1;
        int r    = (id >> 1) & 31;
        int k16  = (id >> 6) & 63;
        int hl   = id >> 12;
        int grow = ((r >> 3) << 10) + d0 + (r & 7);
        const __half* src =
            (hl ? wlo : whi) + (size_t)grow * D_ + (k16 << 4) + (half << 3);
        cpa16(WS + hl * 65536 + (k16 << 10) + (r << 5) + (half << 4), src);
    }
    cp_commit();
    float creg = __ldg(c0 + (size_t)pb * D_ + d0 + pd);
    cp_wait0();
    __syncthreads();

    const unsigned aoff  = (unsigned)(((mt << 4) + (lane & 15)) * 32 + (((lane >> 4) & 1) << 4));
    const unsigned boff0 = (unsigned)(((nh << 4) + (lane & 7)) * 32 + (((lane >> 3) & 1) << 4));
    const unsigned boff1 = boff0 + 8 * 32;

    int pidx[4];
#pragma unroll
    for (int g = 0; g < 4; g++) {
        int n = (g << 3) + pd;
        int pmt = pb >> 4, pgid = pb & 7, prb = (pb >> 3) & 1;
        int pnh = n >> 4, pnt = (n >> 3) & 1, ptig = (n >> 1) & 3, prn = n & 1;
        int pw8 = (pnh << 2) | pmt;
        int pln = (pgid << 2) | ptig;
        int pr  = (prb << 1) | prn;
        pidx[g] = (pw8 << 8) + (pln << 3) + (pnt << 2) + pr;
    }

    for (int t = 0; t < T_; t++) {
        const __half* ah = t ? sfh + (size_t)(t - 1) * BD_ : h0f;
        const float* xgt = xg + (size_t)t * B_ * D4_;

        float xv[4];
#pragma unroll
        for (int g = 0; g < 4; g++)
            xv[g] = __ldg(xgt + (size_t)pb * D4_ + (g << 10) + d0 + pd);

        if (t > 0) {
            if (tid == 0)
                while (*((volatile unsigned*)&g_cnt) < (unsigned)t * gridDim.x) { }
            __syncthreads();
        }

        float acc[2][4];
#pragma unroll
        for (int nt = 0; nt < 2; nt++)
#pragma unroll
            for (int r = 0; r < 4; r++) acc[nt][r] = 0.f;

        // stage chunk ii for both k-halves: 2 x 8KB
        auto issue = [&](int ii) {
            unsigned bA = (unsigned)((ii & 1) * 8192);
#pragma unroll
            for (int j = 0; j < 2; j++) {
                int id  = tid + (j << 9);      // 0..1023
                int ch  = id >> 9;
                int e   = id & 511;
                int row = e >> 3;
                int seg = e & 7;
                int ck  = (ch << 3) + ii;
                const __half* src = ah + (size_t)row * D_ + (ck << 6) + (seg << 3);
                cpa16(HS + (unsigned)(ch * 16384) + bA
                      + (unsigned)(((seg >> 1) << 11) + (row << 5) + ((seg & 1) << 4)), src);
            }
            cp_commit();
        };

        issue(0);
        for (int i = 0; i < 8; i++) {
            cp_wait0();
            __syncthreads();
            if (i < 7) issue(i + 1);
            const unsigned hb = HS + (unsigned)(kh2 * 16384 + (i & 1) * 8192);
#pragma unroll
            for (int k16l = 0; k16l < 4; k16l++) {
                unsigned a[4], bh0[2], bh1[2], bl0[2], bl1[2];
                ldsm_x4(a, hb + (k16l << 11) + aoff);
                unsigned kb = WS + (unsigned)(((kh2 << 5) + (i << 2) + k16l) << 10);
                ldsm_x2(bh0, kb + boff0);
                ldsm_x2(bh1, kb + boff1);
                ldsm_x2(bl0, kb + 65536 + boff0);
                ldsm_x2(bl1, kb + 65536 + boff1);
                mma16816h(acc[0], a, bh0);
                mma16816h(acc[0], a, bl0);
                mma16816h(acc[1], a, bh1);
                mma16816h(acc[1], a, bl1);
            }
        }

        {
            float4* r2 = (float4*)(red2 + (kh2 << 11));
            int base4 = ((w8 << 8) + (lane << 3)) >> 2;
            r2[base4]     = make_float4(acc[0][0], acc[0][1], acc[0][2], acc[0][3]);
            r2[base4 + 1] = make_float4(acc[1][0], acc[1][1], acc[1][2], acc[1][3]);
        }
        __syncthreads();

        {
            float ig = red2[pidx[0]] + red2[2048 + pidx[0]] + xv[0];
            float fg = red2[pidx[1]] + red2[2048 + pidx[1]] + xv[1];
            float gg = red2[pidx[2]] + red2[2048 + pidx[2]] + xv[2];
            float og = red2[pidx[3]] + red2[2048 + pidx[3]] + xv[3];
            float i_ = 1.f / (1.f + __expf(-ig));
            float f_ = 1.f / (1.f + __expf(-fg));
            float o_ = 1.f / (1.f + __expf(-og));
            float cn = f_ * creg + i_ * tanhf(gg);
            float hn = o_ * tanhf(cn);
            creg = cn;
            size_t idx = (size_t)t * BD_ + (size_t)pb * D_ + d0 + pd;
            float hh = __bfloat162float(__float2bfloat16(hn));
            shh[idx] = __float2bfloat16(hh);
            shl[idx] = __float2bfloat16(hn - hh);
            sfh[idx] = __float2half_rn(hn);
            if (t == T_ - 1) hn_out[(size_t)pb * D_ + d0 + pd] = hn;
        }

        if (t < T_ - 1) {
            __threadfence();
            __syncthreads();
            if (tid == 0) atomicAdd(&g_cnt, 1u);
        }
    }

    cn_out[(size_t)pb * D_ + d0 + pd] = creg;

    __threadfence();
    __syncthreads();
    if (tid == 0) {
        unsigned d = atomicAdd(&g_done, 1u) + 1;
        if (d == gridDim.x) {
            g_cnt = 0;
            g_done = 0;
            __threadfence();
        }
    }
}

// ---------------- attention ----------------
__global__ __launch_bounds__(256)
void attn_kernel(const float* __restrict__ q,
                 const float* __restrict__ ctx,
                 const __nv_bfloat16* __restrict__ xh,
                 const __nv_bfloat16* __restrict__ xl,
                 __nv_bfloat16* __restrict__ cath,
                 __nv_bfloat16* __restrict__ catl,
                 float* __restrict__ attn_out)
{
    const int b = blockIdx.x;
    const int t = blockIdx.y;
    const int tb = t * B_ + b;
    __shared__ float qs[D_];
    __shared__ float sc[S_];

    const int tid = threadIdx.x;
    const int warp = tid >> 5, lane = tid & 31;

    ((float4*)qs)[tid] = ((const float4*)(q + (size_t)tb * D_))[tid];
    __syncthreads();

#pragma unroll
    for (int si = 0; si < 8; si++) {
        int s = warp * 8 + si;
        const float4* crow = (const float4*)(ctx + (size_t)(s * B_ + b) * D_);
        float sum = 0.f;
#pragma unroll
        for (int i = 0; i < 8; i++) {
            float4 cv = crow[lane + 32 * i];
            float4 qv = ((const float4*)qs)[lane + 32 * i];
            sum = fmaf(cv.x, qv.x, sum);
            sum = fmaf(cv.y, qv.y, sum);
            sum = fmaf(cv.z, qv.z, sum);
            sum = fmaf(cv.w, qv.w, sum);
        }
#pragma unroll
        for (int off = 16; off; off >>= 1)
            sum += __shfl_down_sync(0xffffffffu, sum, off);
        if (lane == 0) sc[s] = sum;
    }
    __syncthreads();

    if (warp == 0) {
        float v0 = sc[lane], v1 = sc[lane + 32];
        float m = fmaxf(v0, v1);
#pragma unroll
        for (int off = 16; off; off >>= 1)
            m = fmaxf(m, __shfl_xor_sync(0xffffffffu, m, off));
        float e0 = __expf(v0 - m), e1 = __expf(v1 - m);
        float ssum = e0 + e1;
#pragma unroll
        for (int off = 16; off; off >>= 1)
            ssum += __shfl_xor_sync(0xffffffffu, ssum, off);
        float inv = 1.f / ssum;
        sc[lane] = e0 * inv;
        sc[lane + 32] = e1 * inv;
    }
    __syncthreads();

    float4 accv = make_float4(0.f, 0.f, 0.f, 0.f);
    for (int s = 0; s < S_; s++) {
        float a = sc[s];
        float4 cv = ((const float4*)(ctx + (size_t)(s * B_ + b) * D_))[tid];
        accv.x = fmaf(a, cv.x, accv.x);
        accv.y = fmaf(a, cv.y, accv.y);
        accv.z = fmaf(a, cv.z, accv.z);
        accv.w = fmaf(a, cv.w, accv.w);
    }
    __nv_bfloat162* ch = (__nv_bfloat162*)(cath + (size_t)tb * 2 * D_);
    __nv_bfloat162* cl = (__nv_bfloat162*)(catl + (size_t)tb * 2 * D_);
    split_store4(accv, ch + tid * 2, cl + tid * 2);

    const unsigned* xhu = (const unsigned*)(xh + (size_t)tb * D_);
    const unsigned* xlu = (const unsigned*)(xl + (size_t)tb * D_);
    unsigned* chu = (unsigned*)(cath + (size_t)tb * 2 * D_ + D_);
    unsigned* clu = (unsigned*)(catl + (size_t)tb * 2 * D_ + D_);
    chu[tid] = xhu[tid]; chu[tid + 256] = xhu[tid + 256];
    clu[tid] = xlu[tid]; clu[tid + 256] = xlu[tid + 256];

    if (t == T_ - 1 && tid < S_) attn_out[b * S_ + tid] = sc[tid];
}

// ---------------- launch ----------------
extern "C" void kernel_launch(void* const* d_in, const int* in_sizes, int n_in,
                              void* d_out, int out_size)
{
    (void)in_sizes; (void)n_in; (void)out_size;

    const int*   input = (const int*)  d_in[0];
    const float* h0    = (const float*)d_in[1];
    const float* c0    = (const float*)d_in[2];
    const float* ctx   = (const float*)d_in[3];
    const float* emb   = (const float*)d_in[5];
    const float* wih0  = (const float*)d_in[6];
    const float* whh0  = (const float*)d_in[7];
    const float* bih0  = (const float*)d_in[8];
    const float* bhh0  = (const float*)d_in[9];
    const float* wih1  = (const float*)d_in[10];
    const float* whh1  = (const float*)d_in[11];
    const float* bih1  = (const float*)d_in[12];
    const float* bhh1  = (const float*)d_in[13];
    const float* w_in  = (const float*)d_in[14];
    const float* w_out = (const float*)d_in[15];

    float* out      = (float*)d_out;
    float* out_hn   = out + (size_t)TB_ * D_;
    float* out_cn   = out_hn + (size_t)2 * BD_;
    float* out_attn = out_cn + (size_t)2 * BD_;

    float *xg, *q;
    cudaGetSymbolAddress((void**)&xg, g_xg);
    cudaGetSymbolAddress((void**)&q,  g_q);

    __nv_bfloat16 *x0h, *x0l, *sh, *sl, *cath, *catl;
    __nv_bfloat16 *wihh0, *wihl0, *wihh1, *wihl1, *winh, *winl, *wouth, *woutl;
    __half *sf, *h0f, *whhh0, *whhl0, *whhh1, *whhl1;
    cudaGetSymbolAddress((void**)&x0h, g_x0h);   cudaGetSymbolAddress((void**)&x0l, g_x0l);
    cudaGetSymbolAddress((void**)&sh,  g_sh);    cudaGetSymbolAddress((void**)&sl,  g_sl);
    cudaGetSymbolAddress((void**)&sf,  g_sf);    cudaGetSymbolAddress((void**)&h0f, g_h0f);
    cudaGetSymbolAddress((void**)&cath, g_cath); cudaGetSymbolAddress((void**)&catl, g_catl);
    cudaGetSymbolAddress((void**)&whhh0, g_whhh0); cudaGetSymbolAddress((void**)&whhl0, g_whhl0);
    cudaGetSymbolAddress((void**)&whhh1, g_whhh1); cudaGetSymbolAddress((void**)&whhl1, g_whhl1);
    cudaGetSymbolAddress((void**)&wihh0, g_wihh0); cudaGetSymbolAddress((void**)&wihl0, g_wihl0);
    cudaGetSymbolAddress((void**)&wihh1, g_wihh1); cudaGetSymbolAddress((void**)&wihl1, g_wihl1);
    cudaGetSymbolAddress((void**)&winh,  g_winh);  cudaGetSymbolAddress((void**)&winl,  g_winl);
    cudaGetSymbolAddress((void**)&wouth, g_wouth); cudaGetSymbolAddress((void**)&woutl, g_woutl);

    static int smem_set = 0;
    if (!smem_set) {
        cudaFuncSetAttribute(lstm_layer_persist,
                             cudaFuncAttributeMaxDynamicSharedMemorySize, LSTM_SMEM);
        cudaFuncSetAttribute(hgemm_nt<0>,
                             cudaFuncAttributeMaxDynamicSharedMemorySize, HG_SMEM);
        cudaFuncSetAttribute(hgemm_nt<1>,
                             cudaFuncAttributeMaxDynamicSharedMemorySize, HG_SMEM);
        cudaFuncSetAttribute(hgemm_nt<2>,
                             cudaFuncAttributeMaxDynamicSharedMemorySize, HG_SMEM);
        smem_set = 1;
    }

    const size_t BD = (size_t)BD_;

    fused_split<<<(FS_TOTAL + 255) / 256, 256>>>(
        whh0, wih0, whh1, wih1, w_in, w_out, h0,
        whhh0, whhl0, wihh0, wihl0, whhh1, whhl1, wihh1, wihl1,
        winh, winl, wouth, woutl, h0f);
    embed_kernel<<<TB_, 256>>>(input, emb, x0h, x0l);

    hgemm_nt<1><<<dim3(D4_ / 128, TB_ / 128), 256, HG_SMEM>>>(
        x0h, x0l, wihh0, wihl0, xg, TB_, D4_, D_, bih0, bhh0);
    lstm_layer_persist<<<128, 512, LSTM_SMEM>>>(
        h0f, whhh0, whhl0, c0, xg, sh, sl, sf, out_hn, out_cn);

    hgemm_nt<1><<<dim3(D4_ / 128, TB_ / 128), 256, HG_SMEM>>>(
        sh, sl, wihh1, wihl1, xg, TB_, D4_, D_, bih1, bhh1);
    lstm_layer_persist<<<128, 512, LSTM_SMEM>>>(
        h0f + BD, whhh1, whhl1, c0 + BD, xg, sh, sl, sf,
        out_hn + BD, out_cn + BD);

    hgemm_nt<0><<<dim3(D_ / 128, TB_ / 128), 256, HG_SMEM>>>(
        sh, sl, winh, winl, q, TB_, D_, D_, nullptr, nullptr);
    attn_kernel<<<dim3(B_, T_), 256>>>(q, ctx, sh, sl, cath, catl, out_attn);
    hgemm_nt<2><<<dim3(D_ / 128, TB_ / 128), 256, HG_SMEM>>>(
        cath, catl, wouth, woutl, out, TB_, D_, 2 * D_, nullptr, nullptr);
}